// round 12
// baseline (speedup 1.0000x reference)
#include <cuda_runtime.h>
#include <cuda_bf16.h>
#include <cstdint>

#define EPSV 1e-5f
#define B_DIM 4096
#define F_DIM 4096
#define H_DIM 32768
#define W_ELEMS ((size_t)H_DIM * (size_t)F_DIM)   // 134217728

// ---------------- scratch (device globals: no allocation allowed) ----------------
__device__ __nv_bfloat16 g_wq_enc[W_ELEMS];                    // ternary enc_w bf16 [H,F]
__device__ __nv_bfloat16 g_wq_dec[W_ELEMS];                    // ternary dec_w bf16 [F,H]
__device__ __nv_bfloat16 g_xq[(size_t)B_DIM * F_DIM];          // int-valued x bf16 [B,F]
__device__ __nv_bfloat16 g_fq[(size_t)B_DIM * H_DIM];          // int-valued f bf16 [B,H]
__device__ float  g_psum[1024ull * 128 * 128];                 // per-tile split-K partials (64MB)
__device__ int    g_cnt[1024];                                 // per-tile arrival counters (0-init)
__device__ int    g_flag[1024];                                // per-tile data-ready flags (0-init)
__device__ float  g_xinv[B_DIM];
__device__ float  g_finv[B_DIM];
__device__ unsigned g_fmax[B_DIM];                             // row max of f (uint bits)
__device__ double g_wsum[2];                                   // 0-init; reset by finalize
__device__ float  g_dq[2];

// ---------------- helpers ----------------
__device__ __forceinline__ uint32_t smem_u32(const void* p) {
    return (uint32_t)__cvta_generic_to_shared(p);
}
__device__ __forceinline__ void cp16(uint32_t saddr, const void* g) {
    asm volatile("cp.async.cg.shared.global [%0], [%1], 16;\n" :: "r"(saddr), "l"(g) : "memory");
}
#define CP_COMMIT() asm volatile("cp.async.commit_group;\n" ::: "memory")
#define CP_WAIT1()  asm volatile("cp.async.wait_group 1;\n" ::: "memory")

__device__ __forceinline__ float block_reduce_max(float v) {
    __shared__ float sh[32];
    int lane = threadIdx.x & 31, wid = threadIdx.x >> 5;
#pragma unroll
    for (int o = 16; o; o >>= 1) v = fmaxf(v, __shfl_xor_sync(0xffffffffu, v, o));
    if (lane == 0) sh[wid] = v;
    __syncthreads();
    int nw = blockDim.x >> 5;
    if (wid == 0) {
        v = (lane < nw) ? sh[lane] : 0.0f;
#pragma unroll
        for (int o = 16; o; o >>= 1) v = fmaxf(v, __shfl_xor_sync(0xffffffffu, v, o));
        if (lane == 0) sh[0] = v;
    }
    __syncthreads();
    return sh[0];
}

__device__ __forceinline__ uint2 tern_pack(float4 v, float scale) {
    float q0 = fminf(fmaxf(rintf(v.x * scale), -1.f), 1.f);
    float q1 = fminf(fmaxf(rintf(v.y * scale), -1.f), 1.f);
    float q2 = fminf(fmaxf(rintf(v.z * scale), -1.f), 1.f);
    float q3 = fminf(fmaxf(rintf(v.w * scale), -1.f), 1.f);
    __nv_bfloat162 p0 = __floats2bfloat162_rn(q0, q1);
    __nv_bfloat162 p1 = __floats2bfloat162_rn(q2, q3);
    uint2 pk;
    pk.x = *reinterpret_cast<uint32_t*>(&p0);
    pk.y = *reinterpret_cast<uint32_t*>(&p1);
    return pk;
}

__device__ __forceinline__ void abssum_body(const float* __restrict__ w, int which,
                                            size_t bid, size_t nblocks, int nthreads) {
    const size_t n4 = W_ELEMS / 4;
    const float4* w4 = (const float4*)w;
    float s = 0.f;
    for (size_t i = bid * nthreads + threadIdx.x; i < n4; i += nblocks * nthreads) {
        float4 v = w4[i];
        s += fabsf(v.x) + fabsf(v.y) + fabsf(v.z) + fabsf(v.w);
    }
    double d = (double)s;
#pragma unroll
    for (int o = 16; o; o >>= 1) d += __shfl_xor_sync(0xffffffffu, d, o);
    __shared__ double sh[32];
    int lane = threadIdx.x & 31, wid = threadIdx.x >> 5;
    if (lane == 0) sh[wid] = d;
    __syncthreads();
    if (wid == 0) {
        d = (lane < (nthreads >> 5)) ? sh[lane] : 0.0;
#pragma unroll
        for (int o = 16; o; o >>= 1) d += __shfl_xor_sync(0xffffffffu, d, o);
        if (lane == 0) atomicAdd(&g_wsum[which], d);
    }
}

// ---------------- small kernels ----------------
__global__ void finalize_kernel(int which) {
    g_dq[which] = fmaxf((float)(g_wsum[which] / (double)W_ELEMS), EPSV);
    g_wsum[which] = 0.0;
}

// launch 0: blocks [0,4096) xquant rows; blocks [4096,6144) abssum enc_w
#define XA_AS 2048
__global__ void xa_combo(const float* __restrict__ x, const float* __restrict__ dec_b,
                         const float* __restrict__ enc_w) {
    if (blockIdx.x >= B_DIM) {
        abssum_body(enc_w, 0, blockIdx.x - B_DIM, XA_AS, blockDim.x);
        return;
    }
    int row = blockIdx.x;
    if (threadIdx.x == 0) g_fmax[row] = 0u;
    const float4* xr = (const float4*)(x + (size_t)row * F_DIM);
    const float4* db = (const float4*)dec_b;
    const int n4 = F_DIM / 4;
    float m = 0.f;
    for (int i = threadIdx.x; i < n4; i += blockDim.x) {
        float4 v = xr[i], b = db[i];
        m = fmaxf(m, fmaxf(fmaxf(fabsf(v.x - b.x), fabsf(v.y - b.y)),
                           fmaxf(fabsf(v.z - b.z), fabsf(v.w - b.w))));
    }
    m = block_reduce_max(m);
    float scale = 127.0f / fmaxf(m, EPSV);
    if (threadIdx.x == 0) g_xinv[row] = 1.0f / scale;
    uint2* qr = (uint2*)(g_xq + (size_t)row * F_DIM);
    for (int i = threadIdx.x; i < n4; i += blockDim.x) {
        float4 v = xr[i], b = db[i];
        float q0 = fminf(fmaxf(rintf((v.x - b.x) * scale), -128.f), 127.f);
        float q1 = fminf(fmaxf(rintf((v.y - b.y) * scale), -128.f), 127.f);
        float q2 = fminf(fmaxf(rintf((v.z - b.z) * scale), -128.f), 127.f);
        float q3 = fminf(fmaxf(rintf((v.w - b.w) * scale), -128.f), 127.f);
        __nv_bfloat162 p0 = __floats2bfloat162_rn(q0, q1);
        __nv_bfloat162 p1 = __floats2bfloat162_rn(q2, q3);
        uint2 pk;
        pk.x = *reinterpret_cast<uint32_t*>(&p0);
        pk.y = *reinterpret_cast<uint32_t*>(&p1);
        qr[i] = pk;
    }
}

// launch 2: blocks [0, 8192) quantize enc_w; blocks [8192, 10240) abssum dec_w
#define COMBO_WQ 8192
#define COMBO_AS 2048
__global__ void combo_kernel(const float* __restrict__ enc_w,
                             const float* __restrict__ dec_w) {
    if (blockIdx.x < COMBO_WQ) {
        const float scale = 1.0f / g_dq[0];
        const size_t n4 = W_ELEMS / 4;
        const float4* w4 = (const float4*)enc_w;
        uint2* q4 = (uint2*)g_wq_enc;
        for (size_t i = (size_t)blockIdx.x * blockDim.x + threadIdx.x; i < n4;
             i += (size_t)COMBO_WQ * blockDim.x) {
            q4[i] = tern_pack(w4[i], scale);
        }
    } else {
        abssum_body(dec_w, 1, blockIdx.x - COMBO_WQ, COMBO_AS, blockDim.x);
    }
}

__global__ void wquant_kernel(const float* __restrict__ w, int which) {
    __nv_bfloat16* q = which ? g_wq_dec : g_wq_enc;
    float scale = 1.0f / g_dq[which];
    const size_t n4 = W_ELEMS / 4;
    const float4* w4 = (const float4*)w;
    uint2* q4 = (uint2*)q;
    for (size_t i = blockIdx.x * (size_t)blockDim.x + threadIdx.x; i < n4;
         i += (size_t)gridDim.x * blockDim.x) {
        q4[i] = tern_pack(w4[i], scale);
    }
}

// single pass: row max from g_fmax (filled by enc epilogue)
__global__ void fquant_kernel(const float* __restrict__ f) {
    int row = blockIdx.x;
    const float4* fr = (const float4*)(f + (size_t)row * H_DIM);
    const int n4 = H_DIM / 4;
    float m = __uint_as_float(g_fmax[row]);
    float scale = 127.0f / fmaxf(m, EPSV);
    if (threadIdx.x == 0) g_finv[row] = 1.0f / scale;
    uint2* qr = (uint2*)(g_fq + (size_t)row * H_DIM);
    for (int i = threadIdx.x; i < n4; i += blockDim.x) {
        float4 v = fr[i];
        float q0 = fminf(fmaxf(rintf(v.x * scale), -128.f), 127.f);
        float q1 = fminf(fmaxf(rintf(v.y * scale), -128.f), 127.f);
        float q2 = fminf(fmaxf(rintf(v.z * scale), -128.f), 127.f);
        float q3 = fminf(fmaxf(rintf(v.w * scale), -128.f), 127.f);
        __nv_bfloat162 p0 = __floats2bfloat162_rn(q0, q1);
        __nv_bfloat162 p1 = __floats2bfloat162_rn(q2, q3);
        uint2 pk;
        pk.x = *reinterpret_cast<uint32_t*>(&p0);
        pk.y = *reinterpret_cast<uint32_t*>(&p1);
        qr[i] = pk;
    }
}

// ---------------- bf16 GEMM: CTA 128x128, 4 warps of 64x64, BK=64, 3-stage ----------
// MODE 0: enc epilogue (scale+bias+relu + row-max atomic).
// MODE 1: dec with FUSED split-K reduction (first CTA stores partials, second finishes).
#define BM 128
#define BN 128
#define BKB 128
#define NSTAGE 3
#define A_TILE_B (BM * BKB)                // 16 KB
#define STAGE_B (2 * A_TILE_B)             // 32 KB
#define SMEM_GEMM (NSTAGE * STAGE_B)       // 96 KB

__device__ __forceinline__ uint32_t swz(uint32_t row, uint32_t colByte) {
    return row * 128u + (colByte ^ ((row & 7u) * 16u));
}

template <int MODE>
__global__ __launch_bounds__(128, 2)
void gemm_kernel(float* __restrict__ C, const float* __restrict__ bias,
                 int N, int K, int which) {
    extern __shared__ char smem[];
    const uint32_t sbase = smem_u32(smem);

    const __nv_bfloat16* __restrict__ A  = which ? g_fq     : g_xq;
    const __nv_bfloat16* __restrict__ Bw = which ? g_wq_dec : g_wq_enc;
    const float* __restrict__ rowScale   = which ? g_finv   : g_xinv;

    const int tid  = threadIdx.x;
    const int lane = tid & 31;
    const int warp = tid >> 5;     // 0..3
    const int wm = warp >> 1;      // 0..1
    const int wn = warp & 1;       // 0..1
    const int mBase = blockIdx.x * BM;
    const int nBase = blockIdx.y * BN;

    const int kOff = (MODE == 1) ? (int)blockIdx.z * (K >> 1) : 0;
    const int kLen = (MODE == 1) ? (K >> 1) : K;

    // ---- global->shared mapping ----
    const int crow = tid >> 3;
    const int ckb  = (tid & 7) * 16;
    const size_t rowB = (size_t)K * 2;
    const char* gA = (const char*)A  + (size_t)(mBase + crow) * rowB + (size_t)kOff * 2 + ckb;
    const char* gB = (const char*)Bw + (size_t)(nBase + crow) * rowB + (size_t)kOff * 2 + ckb;
    const uint32_t sOff = swz(crow, ckb);

    uint32_t stage[NSTAGE];
#pragma unroll
    for (int s = 0; s < NSTAGE; s++) stage[s] = sbase + s * STAGE_B;

    const int nkt = kLen / 64;

    auto load_stage = [&](int slot, int kt) {
        const uint32_t sa = stage[slot] + sOff;
        const uint32_t sb = sa + A_TILE_B;
        const char* ga = gA + (size_t)kt * BKB;
        const char* gb = gB + (size_t)kt * BKB;
#pragma unroll
        for (int i = 0; i < 8; i++) {
            cp16(sa + i * (16 * 128), ga + (size_t)i * 16 * rowB);
            cp16(sb + i * (16 * 128), gb + (size_t)i * 16 * rowB);
        }
    };

    const uint32_t aRow = wm * 64 + (lane & 15);
    const uint32_t aColH = (lane >> 4) * 16;
    const uint32_t bRow = wn * 64 + (lane & 7) + ((lane >> 4) & 1) * 8;
    const uint32_t bColH = ((lane >> 3) & 1) * 16;

    float acc[4][8][4];
#pragma unroll
    for (int mi = 0; mi < 4; mi++)
#pragma unroll
        for (int ni = 0; ni < 8; ni++)
#pragma unroll
            for (int r = 0; r < 4; r++) acc[mi][ni][r] = 0.f;

    load_stage(0, 0); CP_COMMIT();
    if (nkt > 1) { load_stage(1, 1); }
    CP_COMMIT();

    int slot = 0;
    for (int kt = 0; kt < nkt; kt++) {
        CP_WAIT1();
        __syncthreads();
        {
            const int ldk = kt + 2;
            if (ldk < nkt) {
                int ps = slot + 2; if (ps >= NSTAGE) ps -= NSTAGE;
                load_stage(ps, ldk);
            }
            CP_COMMIT();
        }

        const uint32_t sA = stage[slot];
        const uint32_t sB = stage[slot] + A_TILE_B;

#pragma unroll
        for (int ks = 0; ks < 4; ks++) {
            uint32_t a[4][4];
#pragma unroll
            for (int mi = 0; mi < 4; mi++) {
                const uint32_t addr = sA + swz(aRow + mi * 16, ks * 32 + aColH);
                asm volatile("ldmatrix.sync.aligned.m8n8.x4.shared.b16 {%0,%1,%2,%3}, [%4];\n"
                             : "=r"(a[mi][0]), "=r"(a[mi][1]), "=r"(a[mi][2]), "=r"(a[mi][3])
                             : "r"(addr));
            }
            uint32_t b[4][4];
#pragma unroll
            for (int nb = 0; nb < 4; nb++) {
                const uint32_t addr = sB + swz(bRow + nb * 16, ks * 32 + bColH);
                asm volatile("ldmatrix.sync.aligned.m8n8.x4.shared.b16 {%0,%1,%2,%3}, [%4];\n"
                             : "=r"(b[nb][0]), "=r"(b[nb][1]), "=r"(b[nb][2]), "=r"(b[nb][3])
                             : "r"(addr));
            }
#pragma unroll
            for (int mi = 0; mi < 4; mi++) {
#pragma unroll
                for (int ni = 0; ni < 8; ni++) {
                    const int nb = ni >> 1, pp = (ni & 1) * 2;
                    asm volatile(
                        "mma.sync.aligned.m16n8k16.row.col.f32.bf16.bf16.f32 "
                        "{%0,%1,%2,%3}, {%4,%5,%6,%7}, {%8,%9}, {%0,%1,%2,%3};\n"
                        : "+f"(acc[mi][ni][0]), "+f"(acc[mi][ni][1]),
                          "+f"(acc[mi][ni][2]), "+f"(acc[mi][ni][3])
                        : "r"(a[mi][0]), "r"(a[mi][1]), "r"(a[mi][2]), "r"(a[mi][3]),
                          "r"(b[nb][pp]), "r"(b[nb][pp + 1]));
                }
            }
        }
        if (++slot == NSTAGE) slot = 0;
    }

    // ---- epilogue ----
    const int lr0 = wm * 64 + (lane >> 2);        // local row base (0..127 with +mi*16+half*8)
    const int lc0 = wn * 64 + (lane & 3) * 2;     // local col base

    if (MODE == 1) {
        // fused split-K: first-arriving CTA stores partials, second finishes the tile
        const int tileId = (int)blockIdx.y * (int)gridDim.x + (int)blockIdx.x;
        float* tbuf = g_psum + (size_t)tileId * (BM * BN);
        __shared__ int s_role;
        if (tid == 0) s_role = atomicAdd(&g_cnt[tileId], 1);
        __syncthreads();

        if (s_role == 0) {
            // write raw partials (exact integers in f32)
#pragma unroll
            for (int mi = 0; mi < 4; mi++) {
#pragma unroll
                for (int half = 0; half < 2; half++) {
                    const int lr = lr0 + mi * 16 + half * 8;
#pragma unroll
                    for (int ni = 0; ni < 8; ni++) {
                        const int lc = lc0 + ni * 8;
                        *reinterpret_cast<float2*>(tbuf + lr * BN + lc) =
                            make_float2(acc[mi][ni][half * 2 + 0], acc[mi][ni][half * 2 + 1]);
                    }
                }
            }
            __threadfence();
            __syncthreads();
            if (tid == 0) atomicExch(&g_flag[tileId], 1);
        } else {
            if (tid == 0) { while (atomicAdd(&g_flag[tileId], 0) == 0) {} }
            __syncthreads();
            __threadfence();
            const float dq = g_dq[which];
#pragma unroll
            for (int mi = 0; mi < 4; mi++) {
#pragma unroll
                for (int half = 0; half < 2; half++) {
                    const int lr = lr0 + mi * 16 + half * 8;
                    const int row = mBase + lr;
                    const float s = rowScale[row] * dq;
                    float* cp = C + (size_t)row * N;
#pragma unroll
                    for (int ni = 0; ni < 8; ni++) {
                        const int lc = lc0 + ni * 8;
                        const int col = nBase + lc;
                        float2 p = *reinterpret_cast<const float2*>(tbuf + lr * BN + lc);
                        float v0 = (acc[mi][ni][half * 2 + 0] + p.x) * s + bias[col];
                        float v1 = (acc[mi][ni][half * 2 + 1] + p.y) * s + bias[col + 1];
                        *reinterpret_cast<float2*>(cp + col) = make_float2(v0, v1);
                    }
                }
            }
            __syncthreads();
            if (tid == 0) { g_flag[tileId] = 0; g_cnt[tileId] = 0; }  // reset for graph replay
        }
    } else {
        const float dq = g_dq[which];
#pragma unroll
        for (int mi = 0; mi < 4; mi++) {
#pragma unroll
            for (int half = 0; half < 2; half++) {
                const int row = mBase + lr0 + mi * 16 + half * 8;
                const float s = rowScale[row] * dq;
                float* cp = C + (size_t)row * N;
                float rm = 0.f;
#pragma unroll
                for (int ni = 0; ni < 8; ni++) {
                    const int col = nBase + lc0 + ni * 8;
                    float v0 = acc[mi][ni][half * 2 + 0] * s + bias[col];
                    float v1 = acc[mi][ni][half * 2 + 1] * s + bias[col + 1];
                    v0 = fmaxf(v0, 0.f); v1 = fmaxf(v1, 0.f);
                    rm = fmaxf(rm, fmaxf(v0, v1));
                    *reinterpret_cast<float2*>(cp + col) = make_float2(v0, v1);
                }
                rm = fmaxf(rm, __shfl_xor_sync(0xffffffffu, rm, 1));
                rm = fmaxf(rm, __shfl_xor_sync(0xffffffffu, rm, 2));
                if ((lane & 3) == 0) atomicMax(&g_fmax[row], __float_as_uint(rm));
            }
        }
    }
}

// ---------------- launch ----------------
extern "C" void kernel_launch(void* const* d_in, const int* in_sizes, int n_in,
                              void* d_out, int out_size) {
    (void)in_sizes; (void)n_in; (void)out_size;
    const float* x     = (const float*)d_in[0];
    const float* enc_w = (const float*)d_in[1];
    const float* enc_b = (const float*)d_in[2];
    const float* dec_w = (const float*)d_in[3];
    const float* dec_b = (const float*)d_in[4];

    float* xhat = (float*)d_out;                               // [B, F]
    float* fout = (float*)d_out + (size_t)B_DIM * F_DIM;       // [B, H]

    static int attr_set = 0;
    if (!attr_set) {
        cudaFuncSetAttribute(gemm_kernel<0>, cudaFuncAttributeMaxDynamicSharedMemorySize, SMEM_GEMM);
        cudaFuncSetAttribute(gemm_kernel<1>, cudaFuncAttributeMaxDynamicSharedMemorySize, SMEM_GEMM);
        attr_set = 1;
    }

    xa_combo<<<B_DIM + XA_AS, 512>>>(x, dec_b, enc_w);           // 0: xquant || abssum(enc)
    finalize_kernel<<<1, 1>>>(0);                                // 1: dq[0]
    combo_kernel<<<COMBO_WQ + COMBO_AS, 256>>>(enc_w, dec_w);    // 2: wquant(enc) || abssum(dec)
    {
        dim3 grid(B_DIM / BM, H_DIM / BN);                       // 3: enc GEMM (ncu target)
        gemm_kernel<0><<<grid, 128, SMEM_GEMM>>>(fout, enc_b, H_DIM, F_DIM, 0);
    }
    finalize_kernel<<<1, 1>>>(1);                                // 4: dq[1]
    wquant_kernel<<<8192, 256>>>(dec_w, 1);                      // 5: wquant(dec)
    fquant_kernel<<<B_DIM, 512>>>(fout);                         // 6
    {
        dim3 grid(B_DIM / BM, F_DIM / BN, 2);                    // 7: dec GEMM, fused reduction
        gemm_kernel<1><<<grid, 128, SMEM_GEMM>>>(xhat, dec_b, F_DIM, H_DIM, 1);
    }
}

// round 13
// speedup vs baseline: 1.1238x; 1.1238x over previous
#include <cuda_runtime.h>
#include <cuda_bf16.h>
#include <cstdint>

#define EPSV 1e-5f
#define B_DIM 4096
#define F_DIM 4096
#define H_DIM 32768
#define W_ELEMS ((size_t)H_DIM * (size_t)F_DIM)   // 134217728

// ---------------- scratch (device globals: no allocation allowed) ----------------
__device__ __nv_bfloat16 g_wq_enc[W_ELEMS];                    // ternary enc_w bf16 [H,F]
__device__ __nv_bfloat16 g_wq_dec[W_ELEMS];                    // ternary dec_w bf16 [F,H]
__device__ __nv_bfloat16 g_xq[(size_t)B_DIM * F_DIM];          // int-valued x bf16 [B,F]
__device__ __nv_bfloat16 g_fq[(size_t)B_DIM * H_DIM];          // int-valued f bf16 [B,H]
__device__ float  g_psum[2ull * B_DIM * F_DIM];                // dec split-K partials
__device__ float  g_xinv[B_DIM];
__device__ float  g_finv[B_DIM];
__device__ unsigned g_fmax[B_DIM];                             // row max of f (uint bits)
__device__ double g_wsum[2];
__device__ float  g_dq[2];

// ---------------- helpers ----------------
__device__ __forceinline__ uint32_t smem_u32(const void* p) {
    return (uint32_t)__cvta_generic_to_shared(p);
}
__device__ __forceinline__ void cp16(uint32_t saddr, const void* g) {
    asm volatile("cp.async.cg.shared.global [%0], [%1], 16;\n" :: "r"(saddr), "l"(g) : "memory");
}
#define CP_COMMIT() asm volatile("cp.async.commit_group;\n" ::: "memory")
#define CP_WAIT1()  asm volatile("cp.async.wait_group 1;\n" ::: "memory")

__device__ __forceinline__ float block_reduce_max(float v) {
    __shared__ float sh[32];
    int lane = threadIdx.x & 31, wid = threadIdx.x >> 5;
#pragma unroll
    for (int o = 16; o; o >>= 1) v = fmaxf(v, __shfl_xor_sync(0xffffffffu, v, o));
    if (lane == 0) sh[wid] = v;
    __syncthreads();
    int nw = blockDim.x >> 5;
    if (wid == 0) {
        v = (lane < nw) ? sh[lane] : 0.0f;
#pragma unroll
        for (int o = 16; o; o >>= 1) v = fmaxf(v, __shfl_xor_sync(0xffffffffu, v, o));
        if (lane == 0) sh[0] = v;
    }
    __syncthreads();
    return sh[0];
}

// quantize 4 floats to ternary bf16 pair-pack
__device__ __forceinline__ uint2 tern_pack(float4 v, float scale) {
    float q0 = fminf(fmaxf(rintf(v.x * scale), -1.f), 1.f);
    float q1 = fminf(fmaxf(rintf(v.y * scale), -1.f), 1.f);
    float q2 = fminf(fmaxf(rintf(v.z * scale), -1.f), 1.f);
    float q3 = fminf(fmaxf(rintf(v.w * scale), -1.f), 1.f);
    __nv_bfloat162 p0 = __floats2bfloat162_rn(q0, q1);
    __nv_bfloat162 p1 = __floats2bfloat162_rn(q2, q3);
    uint2 pk;
    pk.x = *reinterpret_cast<uint32_t*>(&p0);
    pk.y = *reinterpret_cast<uint32_t*>(&p1);
    return pk;
}

// ---------------- small kernels ----------------
__global__ void abssum_kernel(const float* __restrict__ w, int which) {
    const size_t n4 = W_ELEMS / 4;
    const float4* w4 = (const float4*)w;
    float s = 0.f;
    for (size_t i = blockIdx.x * (size_t)blockDim.x + threadIdx.x; i < n4;
         i += (size_t)gridDim.x * blockDim.x) {
        float4 v = w4[i];
        s += fabsf(v.x) + fabsf(v.y) + fabsf(v.z) + fabsf(v.w);
    }
    double d = (double)s;
#pragma unroll
    for (int o = 16; o; o >>= 1) d += __shfl_xor_sync(0xffffffffu, d, o);
    __shared__ double sh[32];
    int lane = threadIdx.x & 31, wid = threadIdx.x >> 5;
    if (lane == 0) sh[wid] = d;
    __syncthreads();
    if (wid == 0) {
        d = (lane < (int)(blockDim.x >> 5)) ? sh[lane] : 0.0;
#pragma unroll
        for (int o = 16; o; o >>= 1) d += __shfl_xor_sync(0xffffffffu, d, o);
        if (lane == 0) atomicAdd(&g_wsum[which], d);
    }
}

__global__ void finalize_kernel() {
    g_dq[0] = fmaxf((float)(g_wsum[0] / (double)W_ELEMS), EPSV);
    g_dq[1] = fmaxf((float)(g_wsum[1] / (double)W_ELEMS), EPSV);
}

__global__ void wquant_kernel(const float* __restrict__ w, int which) {
    __nv_bfloat16* q = which ? g_wq_dec : g_wq_enc;
    float scale = 1.0f / g_dq[which];
    const size_t n4 = W_ELEMS / 4;
    const float4* w4 = (const float4*)w;
    uint2* q4 = (uint2*)q;
    for (size_t i = blockIdx.x * (size_t)blockDim.x + threadIdx.x; i < n4;
         i += (size_t)gridDim.x * blockDim.x) {
        q4[i] = tern_pack(w4[i], scale);
    }
}

// first launch: also zeroes g_wsum (runs to completion before abssum starts)
__global__ void xquant_kernel(const float* __restrict__ x, const float* __restrict__ dec_b) {
    int row = blockIdx.x;
    if (threadIdx.x == 0) {
        g_fmax[row] = 0u;
        if (row == 0) { g_wsum[0] = 0.0; g_wsum[1] = 0.0; }
    }
    const float4* xr = (const float4*)(x + (size_t)row * F_DIM);
    const float4* db = (const float4*)dec_b;
    const int n4 = F_DIM / 4;
    float m = 0.f;
    for (int i = threadIdx.x; i < n4; i += blockDim.x) {
        float4 v = xr[i], b = db[i];
        m = fmaxf(m, fmaxf(fmaxf(fabsf(v.x - b.x), fabsf(v.y - b.y)),
                           fmaxf(fabsf(v.z - b.z), fabsf(v.w - b.w))));
    }
    m = block_reduce_max(m);
    float scale = 127.0f / fmaxf(m, EPSV);
    if (threadIdx.x == 0) g_xinv[row] = 1.0f / scale;
    uint2* qr = (uint2*)(g_xq + (size_t)row * F_DIM);
    for (int i = threadIdx.x; i < n4; i += blockDim.x) {
        float4 v = xr[i], b = db[i];
        float q0 = fminf(fmaxf(rintf((v.x - b.x) * scale), -128.f), 127.f);
        float q1 = fminf(fmaxf(rintf((v.y - b.y) * scale), -128.f), 127.f);
        float q2 = fminf(fmaxf(rintf((v.z - b.z) * scale), -128.f), 127.f);
        float q3 = fminf(fmaxf(rintf((v.w - b.w) * scale), -128.f), 127.f);
        __nv_bfloat162 p0 = __floats2bfloat162_rn(q0, q1);
        __nv_bfloat162 p1 = __floats2bfloat162_rn(q2, q3);
        uint2 pk;
        pk.x = *reinterpret_cast<uint32_t*>(&p0);
        pk.y = *reinterpret_cast<uint32_t*>(&p1);
        qr[i] = pk;
    }
}

// single pass: row max from g_fmax (filled by enc epilogue)
__global__ void fquant_kernel(const float* __restrict__ f) {
    int row = blockIdx.x;
    const float4* fr = (const float4*)(f + (size_t)row * H_DIM);
    const int n4 = H_DIM / 4;
    float m = __uint_as_float(g_fmax[row]);
    float scale = 127.0f / fmaxf(m, EPSV);
    if (threadIdx.x == 0) g_finv[row] = 1.0f / scale;
    uint2* qr = (uint2*)(g_fq + (size_t)row * H_DIM);
    for (int i = threadIdx.x; i < n4; i += blockDim.x) {
        float4 v = fr[i];
        float q0 = fminf(fmaxf(rintf(v.x * scale), -128.f), 127.f);
        float q1 = fminf(fmaxf(rintf(v.y * scale), -128.f), 127.f);
        float q2 = fminf(fmaxf(rintf(v.z * scale), -128.f), 127.f);
        float q3 = fminf(fmaxf(rintf(v.w * scale), -128.f), 127.f);
        __nv_bfloat162 p0 = __floats2bfloat162_rn(q0, q1);
        __nv_bfloat162 p1 = __floats2bfloat162_rn(q2, q3);
        uint2 pk;
        pk.x = *reinterpret_cast<uint32_t*>(&p0);
        pk.y = *reinterpret_cast<uint32_t*>(&p1);
        qr[i] = pk;
    }
}

// ---------------- bf16 GEMM: CTA 128x128, 4 warps of 64x64, BK=64, 3-stage ----------
// MODE 0: enc epilogue (scale+bias+relu + row-max atomic). MODE 1: raw split-K partials.
#define BM 128
#define BN 128
#define BKB 128                            // bytes per row per stage (64 bf16)
#define NSTAGE 3
#define A_TILE_B (BM * BKB)                // 16 KB
#define STAGE_B (2 * A_TILE_B)             // 32 KB (A + B)
#define SMEM_GEMM (NSTAGE * STAGE_B)       // 96 KB

__device__ __forceinline__ uint32_t swz(uint32_t row, uint32_t colByte) {
    return row * 128u + (colByte ^ ((row & 7u) * 16u));
}

template <int MODE>
__global__ __launch_bounds__(128, 2)
void gemm_kernel(float* __restrict__ C, const float* __restrict__ bias,
                 int N, int K, int which) {
    extern __shared__ char smem[];
    const uint32_t sbase = smem_u32(smem);

    const __nv_bfloat16* __restrict__ A  = which ? g_fq     : g_xq;
    const __nv_bfloat16* __restrict__ Bw = which ? g_wq_dec : g_wq_enc;
    const float* __restrict__ rowScale   = which ? g_finv   : g_xinv;

    const int tid  = threadIdx.x;
    const int lane = tid & 31;
    const int warp = tid >> 5;     // 0..3
    const int wm = warp >> 1;      // 0..1
    const int wn = warp & 1;       // 0..1
    const int mBase = blockIdx.x * BM;
    const int nBase = blockIdx.y * BN;

    // split-K (MODE 1): z selects K half and partial buffer
    const int kOff = (MODE == 1) ? (int)blockIdx.z * (K >> 1) : 0;
    const int kLen = (MODE == 1) ? (K >> 1) : K;
    float* __restrict__ Cout = (MODE == 1)
        ? g_psum + (size_t)blockIdx.z * B_DIM * F_DIM : C;

    // ---- global->shared mapping: 128 threads, 8 chunks A + 8 chunks B per stage ----
    const int crow = tid >> 3;             // 0..15 (+16*i)
    const int ckb  = (tid & 7) * 16;       // byte within 128B row
    const size_t rowB = (size_t)K * 2;     // row stride bytes
    const char* gA = (const char*)A  + (size_t)(mBase + crow) * rowB + (size_t)kOff * 2 + ckb;
    const char* gB = (const char*)Bw + (size_t)(nBase + crow) * rowB + (size_t)kOff * 2 + ckb;
    const uint32_t sOff = swz(crow, ckb);  // row&7 invariant under +16*i

    uint32_t stage[NSTAGE];
#pragma unroll
    for (int s = 0; s < NSTAGE; s++) stage[s] = sbase + s * STAGE_B;

    const int nkt = kLen / 64;

    auto load_stage = [&](int slot, int kt) {
        const uint32_t sa = stage[slot] + sOff;
        const uint32_t sb = sa + A_TILE_B;
        const char* ga = gA + (size_t)kt * BKB;
        const char* gb = gB + (size_t)kt * BKB;
#pragma unroll
        for (int i = 0; i < 8; i++) {
            cp16(sa + i * (16 * 128), ga + (size_t)i * 16 * rowB);
            cp16(sb + i * (16 * 128), gb + (size_t)i * 16 * rowB);
        }
    };

    // ---- ldmatrix lane addressing ----
    const uint32_t aRow = wm * 64 + (lane & 15);                          // + mi*16
    const uint32_t aColH = (lane >> 4) * 16;                              // + ks*32
    const uint32_t bRow = wn * 64 + (lane & 7) + ((lane >> 4) & 1) * 8;   // + nb*16
    const uint32_t bColH = ((lane >> 3) & 1) * 16;                        // + ks*32

    float acc[4][8][4];
#pragma unroll
    for (int mi = 0; mi < 4; mi++)
#pragma unroll
        for (int ni = 0; ni < 8; ni++)
#pragma unroll
            for (int r = 0; r < 4; r++) acc[mi][ni][r] = 0.f;

    // ---- prologue: 2 stages in flight ----
    load_stage(0, 0); CP_COMMIT();
    if (nkt > 1) { load_stage(1, 1); }
    CP_COMMIT();

    int slot = 0;
    for (int kt = 0; kt < nkt; kt++) {
        CP_WAIT1();
        __syncthreads();

        // prefetch kt+2
        {
            const int ldk = kt + 2;
            if (ldk < nkt) {
                int ps = slot + 2; if (ps >= NSTAGE) ps -= NSTAGE;
                load_stage(ps, ldk);
            }
            CP_COMMIT();
        }

        const uint32_t sA = stage[slot];
        const uint32_t sB = stage[slot] + A_TILE_B;

#pragma unroll
        for (int ks = 0; ks < 4; ks++) {
            uint32_t a[4][4];
#pragma unroll
            for (int mi = 0; mi < 4; mi++) {
                const uint32_t addr = sA + swz(aRow + mi * 16, ks * 32 + aColH);
                asm volatile("ldmatrix.sync.aligned.m8n8.x4.shared.b16 {%0,%1,%2,%3}, [%4];\n"
                             : "=r"(a[mi][0]), "=r"(a[mi][1]), "=r"(a[mi][2]), "=r"(a[mi][3])
                             : "r"(addr));
            }
            uint32_t b[4][4];
#pragma unroll
            for (int nb = 0; nb < 4; nb++) {
                const uint32_t addr = sB + swz(bRow + nb * 16, ks * 32 + bColH);
                asm volatile("ldmatrix.sync.aligned.m8n8.x4.shared.b16 {%0,%1,%2,%3}, [%4];\n"
                             : "=r"(b[nb][0]), "=r"(b[nb][1]), "=r"(b[nb][2]), "=r"(b[nb][3])
                             : "r"(addr));
            }
#pragma unroll
            for (int mi = 0; mi < 4; mi++) {
#pragma unroll
                for (int ni = 0; ni < 8; ni++) {
                    const int nb = ni >> 1, pp = (ni & 1) * 2;
                    asm volatile(
                        "mma.sync.aligned.m16n8k16.row.col.f32.bf16.bf16.f32 "
                        "{%0,%1,%2,%3}, {%4,%5,%6,%7}, {%8,%9}, {%0,%1,%2,%3};\n"
                        : "+f"(acc[mi][ni][0]), "+f"(acc[mi][ni][1]),
                          "+f"(acc[mi][ni][2]), "+f"(acc[mi][ni][3])
                        : "r"(a[mi][0]), "r"(a[mi][1]), "r"(a[mi][2]), "r"(a[mi][3]),
                          "r"(b[nb][pp]), "r"(b[nb][pp + 1]));
                }
            }
        }
        if (++slot == NSTAGE) slot = 0;
    }

    // ---- epilogue ----
    const int r0 = mBase + wm * 64 + (lane >> 2);
    const int c0 = nBase + wn * 64 + (lane & 3) * 2;

    if (MODE == 1) {
        // raw split-K partials (exact integers in f32)
#pragma unroll
        for (int mi = 0; mi < 4; mi++) {
#pragma unroll
            for (int half = 0; half < 2; half++) {
                const int row = r0 + mi * 16 + half * 8;
                float* cp = Cout + (size_t)row * N;
#pragma unroll
                for (int ni = 0; ni < 8; ni++) {
                    const int col = c0 + ni * 8;
                    *reinterpret_cast<float2*>(cp + col) =
                        make_float2(acc[mi][ni][half * 2 + 0], acc[mi][ni][half * 2 + 1]);
                }
            }
        }
    } else {
        const float dq = g_dq[which];
#pragma unroll
        for (int mi = 0; mi < 4; mi++) {
#pragma unroll
            for (int half = 0; half < 2; half++) {
                const int row = r0 + mi * 16 + half * 8;
                const float s = rowScale[row] * dq;
                float* cp = Cout + (size_t)row * N;
                float rm = 0.f;
#pragma unroll
                for (int ni = 0; ni < 8; ni++) {
                    const int col = c0 + ni * 8;
                    float v0 = acc[mi][ni][half * 2 + 0] * s + bias[col];
                    float v1 = acc[mi][ni][half * 2 + 1] * s + bias[col + 1];
                    v0 = fmaxf(v0, 0.f); v1 = fmaxf(v1, 0.f);
                    rm = fmaxf(rm, fmaxf(v0, v1));
                    *reinterpret_cast<float2*>(cp + col) = make_float2(v0, v1);
                }
                // row max over the 4 lanes sharing this row, one atomic per row/warp
                rm = fmaxf(rm, __shfl_xor_sync(0xffffffffu, rm, 1));
                rm = fmaxf(rm, __shfl_xor_sync(0xffffffffu, rm, 2));
                if ((lane & 3) == 0) atomicMax(&g_fmax[row], __float_as_uint(rm));
            }
        }
    }
}

// dec finish: xhat = (p0 + p1) * rowScale + dec_b
__global__ void dec_finish(float* __restrict__ xhat, const float* __restrict__ dec_b) {
    const size_t i4 = blockIdx.x * (size_t)blockDim.x + threadIdx.x;   // float4 index
    const int row = (int)(i4 / (F_DIM / 4));
    const int c4 = (int)(i4 % (F_DIM / 4));
    const float s = g_finv[row] * g_dq[1];
    const float4 p0 = ((const float4*)g_psum)[i4];
    const float4 p1 = ((const float4*)g_psum)[i4 + (size_t)B_DIM * F_DIM / 4];
    const float4 b = ((const float4*)dec_b)[c4];
    float4 o;
    o.x = (p0.x + p1.x) * s + b.x;
    o.y = (p0.y + p1.y) * s + b.y;
    o.z = (p0.z + p1.z) * s + b.z;
    o.w = (p0.w + p1.w) * s + b.w;
    ((float4*)xhat)[i4] = o;
}

// ---------------- launch ----------------
extern "C" void kernel_launch(void* const* d_in, const int* in_sizes, int n_in,
                              void* d_out, int out_size) {
    (void)in_sizes; (void)n_in; (void)out_size;
    const float* x     = (const float*)d_in[0];
    const float* enc_w = (const float*)d_in[1];
    const float* enc_b = (const float*)d_in[2];
    const float* dec_w = (const float*)d_in[3];
    const float* dec_b = (const float*)d_in[4];

    float* xhat = (float*)d_out;                               // [B, F]
    float* fout = (float*)d_out + (size_t)B_DIM * F_DIM;       // [B, H]

    static int attr_set = 0;
    if (!attr_set) {
        cudaFuncSetAttribute(gemm_kernel<0>, cudaFuncAttributeMaxDynamicSharedMemorySize, SMEM_GEMM);
        cudaFuncSetAttribute(gemm_kernel<1>, cudaFuncAttributeMaxDynamicSharedMemorySize, SMEM_GEMM);
        attr_set = 1;
    }

    xquant_kernel<<<B_DIM, 512>>>(x, dec_b);                     // 0 (also zeroes g_wsum)
    abssum_kernel<<<2048, 256>>>(enc_w, 0);                      // 1
    abssum_kernel<<<2048, 256>>>(dec_w, 1);                      // 2
    finalize_kernel<<<1, 1>>>();                                 // 3
    wquant_kernel<<<8192, 256>>>(enc_w, 0);                      // 4
    {
        dim3 grid(B_DIM / BM, H_DIM / BN);                       // 5: enc GEMM
        gemm_kernel<0><<<grid, 128, SMEM_GEMM>>>(fout, enc_b, H_DIM, F_DIM, 0);
    }
    wquant_kernel<<<8192, 256>>>(dec_w, 1);                      // 6
    fquant_kernel<<<B_DIM, 512>>>(fout);                         // 7
    {
        dim3 grid(B_DIM / BM, F_DIM / BN, 2);                    // 8: dec GEMM (split-K=2)
        gemm_kernel<1><<<grid, 128, SMEM_GEMM>>>(nullptr, nullptr, F_DIM, H_DIM, 1);
        dec_finish<<<(B_DIM * (F_DIM / 4)) / 256, 256>>>(xhat, dec_b);   // 9
    }
}

// round 14
// speedup vs baseline: 1.1334x; 1.0086x over previous
#include <cuda_runtime.h>
#include <cuda_bf16.h>
#include <cstdint>

#define EPSV 1e-5f
#define B_DIM 4096
#define F_DIM 4096
#define H_DIM 32768
#define W_ELEMS ((size_t)H_DIM * (size_t)F_DIM)   // 134217728

// ---------------- scratch (device globals: no allocation allowed) ----------------
__device__ __nv_bfloat16 g_wq_enc[W_ELEMS];                    // ternary enc_w bf16 [H,F]
__device__ __nv_bfloat16 g_wq_dec[W_ELEMS];                    // ternary dec_w bf16 [F,H]
__device__ __nv_bfloat16 g_xq[(size_t)B_DIM * F_DIM];          // int-valued x bf16 [B,F]
__device__ __nv_bfloat16 g_fq[(size_t)B_DIM * H_DIM];          // int-valued f bf16 [B,H]
__device__ float  g_psum[2ull * B_DIM * F_DIM];                // dec split-K partials
__device__ float  g_xinv[B_DIM];
__device__ float  g_finv[B_DIM];
__device__ unsigned g_fmax[B_DIM];                             // row max of f (uint bits)
__device__ double g_wsum[2];
__device__ float  g_dq[2];

// ---------------- helpers ----------------
__device__ __forceinline__ uint32_t smem_u32(const void* p) {
    return (uint32_t)__cvta_generic_to_shared(p);
}
__device__ __forceinline__ void cp16(uint32_t saddr, const void* g) {
    asm volatile("cp.async.cg.shared.global [%0], [%1], 16;\n" :: "r"(saddr), "l"(g) : "memory");
}
#define CP_COMMIT() asm volatile("cp.async.commit_group;\n" ::: "memory")
#define CP_WAIT1()  asm volatile("cp.async.wait_group 1;\n" ::: "memory")

__device__ __forceinline__ float block_reduce_max(float v) {
    __shared__ float sh[32];
    int lane = threadIdx.x & 31, wid = threadIdx.x >> 5;
#pragma unroll
    for (int o = 16; o; o >>= 1) v = fmaxf(v, __shfl_xor_sync(0xffffffffu, v, o));
    if (lane == 0) sh[wid] = v;
    __syncthreads();
    int nw = blockDim.x >> 5;
    if (wid == 0) {
        v = (lane < nw) ? sh[lane] : 0.0f;
#pragma unroll
        for (int o = 16; o; o >>= 1) v = fmaxf(v, __shfl_xor_sync(0xffffffffu, v, o));
        if (lane == 0) sh[0] = v;
    }
    __syncthreads();
    return sh[0];
}

// quantize 4 floats to ternary bf16 pair-pack
__device__ __forceinline__ uint2 tern_pack(float4 v, float scale) {
    float q0 = fminf(fmaxf(rintf(v.x * scale), -1.f), 1.f);
    float q1 = fminf(fmaxf(rintf(v.y * scale), -1.f), 1.f);
    float q2 = fminf(fmaxf(rintf(v.z * scale), -1.f), 1.f);
    float q3 = fminf(fmaxf(rintf(v.w * scale), -1.f), 1.f);
    __nv_bfloat162 p0 = __floats2bfloat162_rn(q0, q1);
    __nv_bfloat162 p1 = __floats2bfloat162_rn(q2, q3);
    uint2 pk;
    pk.x = *reinterpret_cast<uint32_t*>(&p0);
    pk.y = *reinterpret_cast<uint32_t*>(&p1);
    return pk;
}

// ---------------- small kernels ----------------
__global__ void abssum_kernel(const float* __restrict__ w, int which) {
    const size_t n4 = W_ELEMS / 4;
    const float4* w4 = (const float4*)w;
    float s = 0.f;
    for (size_t i = blockIdx.x * (size_t)blockDim.x + threadIdx.x; i < n4;
         i += (size_t)gridDim.x * blockDim.x) {
        float4 v = w4[i];
        s += fabsf(v.x) + fabsf(v.y) + fabsf(v.z) + fabsf(v.w);
    }
    double d = (double)s;
#pragma unroll
    for (int o = 16; o; o >>= 1) d += __shfl_xor_sync(0xffffffffu, d, o);
    __shared__ double sh[32];
    int lane = threadIdx.x & 31, wid = threadIdx.x >> 5;
    if (lane == 0) sh[wid] = d;
    __syncthreads();
    if (wid == 0) {
        d = (lane < (int)(blockDim.x >> 5)) ? sh[lane] : 0.0;
#pragma unroll
        for (int o = 16; o; o >>= 1) d += __shfl_xor_sync(0xffffffffu, d, o);
        if (lane == 0) atomicAdd(&g_wsum[which], d);
    }
}

__global__ void finalize_kernel(int which) {
    g_dq[which] = fmaxf((float)(g_wsum[which] / (double)W_ELEMS), EPSV);
}

__global__ void wquant_kernel(const float* __restrict__ w, int which) {
    __nv_bfloat16* q = which ? g_wq_dec : g_wq_enc;
    float scale = 1.0f / g_dq[which];
    const size_t n4 = W_ELEMS / 4;
    const float4* w4 = (const float4*)w;
    uint2* q4 = (uint2*)q;
    for (size_t i = blockIdx.x * (size_t)blockDim.x + threadIdx.x; i < n4;
         i += (size_t)gridDim.x * blockDim.x) {
        q4[i] = tern_pack(w4[i], scale);
    }
}

// first launch: also zeroes g_wsum for this replay
__global__ void xquant_kernel(const float* __restrict__ x, const float* __restrict__ dec_b) {
    int row = blockIdx.x;
    if (threadIdx.x == 0) {
        g_fmax[row] = 0u;
        if (row == 0) { g_wsum[0] = 0.0; g_wsum[1] = 0.0; }
    }
    const float4* xr = (const float4*)(x + (size_t)row * F_DIM);
    const float4* db = (const float4*)dec_b;
    const int n4 = F_DIM / 4;
    float m = 0.f;
    for (int i = threadIdx.x; i < n4; i += blockDim.x) {
        float4 v = xr[i], b = db[i];
        m = fmaxf(m, fmaxf(fmaxf(fabsf(v.x - b.x), fabsf(v.y - b.y)),
                           fmaxf(fabsf(v.z - b.z), fabsf(v.w - b.w))));
    }
    m = block_reduce_max(m);
    float scale = 127.0f / fmaxf(m, EPSV);
    if (threadIdx.x == 0) g_xinv[row] = 1.0f / scale;
    uint2* qr = (uint2*)(g_xq + (size_t)row * F_DIM);
    for (int i = threadIdx.x; i < n4; i += blockDim.x) {
        float4 v = xr[i], b = db[i];
        float q0 = fminf(fmaxf(rintf((v.x - b.x) * scale), -128.f), 127.f);
        float q1 = fminf(fmaxf(rintf((v.y - b.y) * scale), -128.f), 127.f);
        float q2 = fminf(fmaxf(rintf((v.z - b.z) * scale), -128.f), 127.f);
        float q3 = fminf(fmaxf(rintf((v.w - b.w) * scale), -128.f), 127.f);
        __nv_bfloat162 p0 = __floats2bfloat162_rn(q0, q1);
        __nv_bfloat162 p1 = __floats2bfloat162_rn(q2, q3);
        uint2 pk;
        pk.x = *reinterpret_cast<uint32_t*>(&p0);
        pk.y = *reinterpret_cast<uint32_t*>(&p1);
        qr[i] = pk;
    }
}

// single pass: row max from g_fmax (filled by enc epilogue)
__global__ void fquant_kernel(const float* __restrict__ f) {
    int row = blockIdx.x;
    const float4* fr = (const float4*)(f + (size_t)row * H_DIM);
    const int n4 = H_DIM / 4;
    float m = __uint_as_float(g_fmax[row]);
    float scale = 127.0f / fmaxf(m, EPSV);
    if (threadIdx.x == 0) g_finv[row] = 1.0f / scale;
    uint2* qr = (uint2*)(g_fq + (size_t)row * H_DIM);
    for (int i = threadIdx.x; i < n4; i += blockDim.x) {
        float4 v = fr[i];
        float q0 = fminf(fmaxf(rintf(v.x * scale), -128.f), 127.f);
        float q1 = fminf(fmaxf(rintf(v.y * scale), -128.f), 127.f);
        float q2 = fminf(fmaxf(rintf(v.z * scale), -128.f), 127.f);
        float q3 = fminf(fmaxf(rintf(v.w * scale), -128.f), 127.f);
        __nv_bfloat162 p0 = __floats2bfloat162_rn(q0, q1);
        __nv_bfloat162 p1 = __floats2bfloat162_rn(q2, q3);
        uint2 pk;
        pk.x = *reinterpret_cast<uint32_t*>(&p0);
        pk.y = *reinterpret_cast<uint32_t*>(&p1);
        qr[i] = pk;
    }
}

// ---------------- bf16 GEMM: CTA 128x128, 4 warps of 64x64, BK=64, 3-stage ----------
// MODE 0: enc epilogue (scale+bias+relu + row-max atomic). MODE 1: raw split-K partials.
#define BM 128
#define BN 128
#define BKB 128                            // bytes per row per stage (64 bf16)
#define NSTAGE 3
#define A_TILE_B (BM * BKB)                // 16 KB
#define STAGE_B (2 * A_TILE_B)             // 32 KB (A + B)
#define SMEM_GEMM (NSTAGE * STAGE_B)       // 96 KB

__device__ __forceinline__ uint32_t swz(uint32_t row, uint32_t colByte) {
    return row * 128u + (colByte ^ ((row & 7u) * 16u));
}

template <int MODE>
__global__ __launch_bounds__(128, 2)
void gemm_kernel(float* __restrict__ C, const float* __restrict__ bias,
                 int N, int K, int which) {
    extern __shared__ char smem[];
    const uint32_t sbase = smem_u32(smem);

    const __nv_bfloat16* __restrict__ A  = which ? g_fq     : g_xq;
    const __nv_bfloat16* __restrict__ Bw = which ? g_wq_dec : g_wq_enc;
    const float* __restrict__ rowScale   = which ? g_finv   : g_xinv;

    const int tid  = threadIdx.x;
    const int lane = tid & 31;
    const int warp = tid >> 5;     // 0..3
    const int wm = warp >> 1;      // 0..1
    const int wn = warp & 1;       // 0..1
    const int mBase = blockIdx.x * BM;
    const int nBase = blockIdx.y * BN;

    // split-K (MODE 1): z selects K half and partial buffer
    const int kOff = (MODE == 1) ? (int)blockIdx.z * (K >> 1) : 0;
    const int kLen = (MODE == 1) ? (K >> 1) : K;
    float* __restrict__ Cout = (MODE == 1)
        ? g_psum + (size_t)blockIdx.z * B_DIM * F_DIM : C;

    // ---- global->shared mapping: 128 threads, 8 chunks A + 8 chunks B per stage ----
    const int crow = tid >> 3;             // 0..15 (+16*i)
    const int ckb  = (tid & 7) * 16;       // byte within 128B row
    const size_t rowB = (size_t)K * 2;     // row stride bytes
    const char* gA = (const char*)A  + (size_t)(mBase + crow) * rowB + (size_t)kOff * 2 + ckb;
    const char* gB = (const char*)Bw + (size_t)(nBase + crow) * rowB + (size_t)kOff * 2 + ckb;
    const uint32_t sOff = swz(crow, ckb);  // row&7 invariant under +16*i

    uint32_t stage[NSTAGE];
#pragma unroll
    for (int s = 0; s < NSTAGE; s++) stage[s] = sbase + s * STAGE_B;

    const int nkt = kLen / 64;

    auto load_stage = [&](int slot, int kt) {
        const uint32_t sa = stage[slot] + sOff;
        const uint32_t sb = sa + A_TILE_B;
        const char* ga = gA + (size_t)kt * BKB;
        const char* gb = gB + (size_t)kt * BKB;
#pragma unroll
        for (int i = 0; i < 8; i++) {
            cp16(sa + i * (16 * 128), ga + (size_t)i * 16 * rowB);
            cp16(sb + i * (16 * 128), gb + (size_t)i * 16 * rowB);
        }
    };

    // ---- ldmatrix lane addressing ----
    const uint32_t aRow = wm * 64 + (lane & 15);                          // + mi*16
    const uint32_t aColH = (lane >> 4) * 16;                              // + ks*32
    const uint32_t bRow = wn * 64 + (lane & 7) + ((lane >> 4) & 1) * 8;   // + nb*16
    const uint32_t bColH = ((lane >> 3) & 1) * 16;                        // + ks*32

    float acc[4][8][4];
#pragma unroll
    for (int mi = 0; mi < 4; mi++)
#pragma unroll
        for (int ni = 0; ni < 8; ni++)
#pragma unroll
            for (int r = 0; r < 4; r++) acc[mi][ni][r] = 0.f;

    // ---- prologue: 2 stages in flight ----
    load_stage(0, 0); CP_COMMIT();
    if (nkt > 1) { load_stage(1, 1); }
    CP_COMMIT();

    int slot = 0;
    for (int kt = 0; kt < nkt; kt++) {
        CP_WAIT1();
        __syncthreads();

        // prefetch kt+2
        {
            const int ldk = kt + 2;
            if (ldk < nkt) {
                int ps = slot + 2; if (ps >= NSTAGE) ps -= NSTAGE;
                load_stage(ps, ldk);
            }
            CP_COMMIT();
        }

        const uint32_t sA = stage[slot];
        const uint32_t sB = stage[slot] + A_TILE_B;

#pragma unroll
        for (int ks = 0; ks < 4; ks++) {
            uint32_t a[4][4];
#pragma unroll
            for (int mi = 0; mi < 4; mi++) {
                const uint32_t addr = sA + swz(aRow + mi * 16, ks * 32 + aColH);
                asm volatile("ldmatrix.sync.aligned.m8n8.x4.shared.b16 {%0,%1,%2,%3}, [%4];\n"
                             : "=r"(a[mi][0]), "=r"(a[mi][1]), "=r"(a[mi][2]), "=r"(a[mi][3])
                             : "r"(addr));
            }
            uint32_t b[4][4];
#pragma unroll
            for (int nb = 0; nb < 4; nb++) {
                const uint32_t addr = sB + swz(bRow + nb * 16, ks * 32 + bColH);
                asm volatile("ldmatrix.sync.aligned.m8n8.x4.shared.b16 {%0,%1,%2,%3}, [%4];\n"
                             : "=r"(b[nb][0]), "=r"(b[nb][1]), "=r"(b[nb][2]), "=r"(b[nb][3])
                             : "r"(addr));
            }
#pragma unroll
            for (int mi = 0; mi < 4; mi++) {
#pragma unroll
                for (int ni = 0; ni < 8; ni++) {
                    const int nb = ni >> 1, pp = (ni & 1) * 2;
                    asm volatile(
                        "mma.sync.aligned.m16n8k16.row.col.f32.bf16.bf16.f32 "
                        "{%0,%1,%2,%3}, {%4,%5,%6,%7}, {%8,%9}, {%0,%1,%2,%3};\n"
                        : "+f"(acc[mi][ni][0]), "+f"(acc[mi][ni][1]),
                          "+f"(acc[mi][ni][2]), "+f"(acc[mi][ni][3])
                        : "r"(a[mi][0]), "r"(a[mi][1]), "r"(a[mi][2]), "r"(a[mi][3]),
                          "r"(b[nb][pp]), "r"(b[nb][pp + 1]));
                }
            }
        }
        if (++slot == NSTAGE) slot = 0;
    }

    // ---- epilogue ----
    const int r0 = mBase + wm * 64 + (lane >> 2);
    const int c0 = nBase + wn * 64 + (lane & 3) * 2;

    if (MODE == 1) {
        // raw split-K partials (exact integers in f32)
#pragma unroll
        for (int mi = 0; mi < 4; mi++) {
#pragma unroll
            for (int half = 0; half < 2; half++) {
                const int row = r0 + mi * 16 + half * 8;
                float* cp = Cout + (size_t)row * N;
#pragma unroll
                for (int ni = 0; ni < 8; ni++) {
                    const int col = c0 + ni * 8;
                    *reinterpret_cast<float2*>(cp + col) =
                        make_float2(acc[mi][ni][half * 2 + 0], acc[mi][ni][half * 2 + 1]);
                }
            }
        }
    } else {
        const float dq = g_dq[which];
#pragma unroll
        for (int mi = 0; mi < 4; mi++) {
#pragma unroll
            for (int half = 0; half < 2; half++) {
                const int row = r0 + mi * 16 + half * 8;
                const float s = rowScale[row] * dq;
                float* cp = Cout + (size_t)row * N;
                float rm = 0.f;
#pragma unroll
                for (int ni = 0; ni < 8; ni++) {
                    const int col = c0 + ni * 8;
                    float v0 = acc[mi][ni][half * 2 + 0] * s + bias[col];
                    float v1 = acc[mi][ni][half * 2 + 1] * s + bias[col + 1];
                    v0 = fmaxf(v0, 0.f); v1 = fmaxf(v1, 0.f);
                    rm = fmaxf(rm, fmaxf(v0, v1));
                    *reinterpret_cast<float2*>(cp + col) = make_float2(v0, v1);
                }
                // row max over the 4 lanes sharing this row, one atomic per row/warp
                rm = fmaxf(rm, __shfl_xor_sync(0xffffffffu, rm, 1));
                rm = fmaxf(rm, __shfl_xor_sync(0xffffffffu, rm, 2));
                if ((lane & 3) == 0) atomicMax(&g_fmax[row], __float_as_uint(rm));
            }
        }
    }
}

// dec finish: xhat = (p0 + p1) * rowScale + dec_b
__global__ void dec_finish(float* __restrict__ xhat, const float* __restrict__ dec_b) {
    const size_t i4 = blockIdx.x * (size_t)blockDim.x + threadIdx.x;   // float4 index
    const int row = (int)(i4 / (F_DIM / 4));
    const int c4 = (int)(i4 % (F_DIM / 4));
    const float s = g_finv[row] * g_dq[1];
    const float4 p0 = ((const float4*)g_psum)[i4];
    const float4 p1 = ((const float4*)g_psum)[i4 + (size_t)B_DIM * F_DIM / 4];
    const float4 b = ((const float4*)dec_b)[c4];
    float4 o;
    o.x = (p0.x + p1.x) * s + b.x;
    o.y = (p0.y + p1.y) * s + b.y;
    o.z = (p0.z + p1.z) * s + b.z;
    o.w = (p0.w + p1.w) * s + b.w;
    ((float4*)xhat)[i4] = o;
}

// ---------------- launch ----------------
extern "C" void kernel_launch(void* const* d_in, const int* in_sizes, int n_in,
                              void* d_out, int out_size) {
    (void)in_sizes; (void)n_in; (void)out_size;
    const float* x     = (const float*)d_in[0];
    const float* enc_w = (const float*)d_in[1];
    const float* enc_b = (const float*)d_in[2];
    const float* dec_w = (const float*)d_in[3];
    const float* dec_b = (const float*)d_in[4];

    float* xhat = (float*)d_out;                               // [B, F]
    float* fout = (float*)d_out + (size_t)B_DIM * F_DIM;       // [B, H]

    static int inited = 0;
    static cudaStream_t s2;
    static cudaEvent_t e1, e2;
    if (!inited) {
        cudaFuncSetAttribute(gemm_kernel<0>, cudaFuncAttributeMaxDynamicSharedMemorySize, SMEM_GEMM);
        cudaFuncSetAttribute(gemm_kernel<1>, cudaFuncAttributeMaxDynamicSharedMemorySize, SMEM_GEMM);
        cudaStreamCreateWithFlags(&s2, cudaStreamNonBlocking);
        cudaEventCreateWithFlags(&e1, cudaEventDisableTiming);
        cudaEventCreateWithFlags(&e2, cudaEventDisableTiming);
        inited = 1;
    }

    // ---- stream 0: x/enc pipeline ----
    xquant_kernel<<<B_DIM, 512>>>(x, dec_b);                     // zeroes wsum[0..1], fmax
    abssum_kernel<<<2048, 256>>>(enc_w, 0);
    finalize_kernel<<<1, 1>>>(0);                                // dq[0]
    wquant_kernel<<<8192, 256>>>(enc_w, 0);

    // ---- fork: dec-weight branch runs concurrently with the enc GEMM ----
    cudaEventRecord(e1, 0);
    cudaStreamWaitEvent(s2, e1, 0);
    abssum_kernel<<<2048, 256, 0, s2>>>(dec_w, 1);
    finalize_kernel<<<1, 1, 0, s2>>>(1);                         // dq[1]
    wquant_kernel<<<8192, 256, 0, s2>>>(dec_w, 1);
    cudaEventRecord(e2, s2);

    // ---- stream 0: enc GEMM (overlapped with the s2 branch) ----
    {
        dim3 grid(B_DIM / BM, H_DIM / BN);
        gemm_kernel<0><<<grid, 128, SMEM_GEMM>>>(fout, enc_b, H_DIM, F_DIM, 0);
    }
    fquant_kernel<<<B_DIM, 512>>>(fout);

    // ---- join, then dec GEMM (split-K=2) + finish ----
    cudaStreamWaitEvent(0, e2, 0);
    {
        dim3 grid(B_DIM / BM, F_DIM / BN, 2);
        gemm_kernel<1><<<grid, 128, SMEM_GEMM>>>(nullptr, nullptr, F_DIM, H_DIM, 1);
        dec_finish<<<(B_DIM * (F_DIM / 4)) / 256, 256>>>(xhat, dec_b);
    }
}

// round 16
// speedup vs baseline: 1.1348x; 1.0012x over previous
#include <cuda_runtime.h>
#include <cuda_bf16.h>
#include <cstdint>

#define EPSV 1e-5f
#define B_DIM 4096
#define F_DIM 4096
#define H_DIM 32768
#define W_ELEMS ((size_t)H_DIM * (size_t)F_DIM)   // 134217728

// ---------------- scratch (device globals: no allocation allowed) ----------------
__device__ __nv_bfloat16 g_wq_enc[W_ELEMS];                    // ternary enc_w bf16 [H,F]
__device__ __nv_bfloat16 g_wq_dec[W_ELEMS];                    // ternary dec_w bf16 [F,H]
__device__ __nv_bfloat16 g_xq[(size_t)B_DIM * F_DIM];          // int-valued x bf16 [B,F]
__device__ __nv_bfloat16 g_fq[(size_t)B_DIM * H_DIM];          // int-valued f bf16 [B,H]
__device__ float  g_psum[2ull * B_DIM * F_DIM];                // dec split-K partials
__device__ float  g_xinv[B_DIM];
__device__ float  g_finv[B_DIM];
__device__ unsigned g_fmax[B_DIM];                             // row max of f (uint bits)
__device__ double g_wsum[2];                                   // 0 at load; finalize resets after use
__device__ float  g_dq[2];

// ---------------- helpers ----------------
__device__ __forceinline__ uint32_t smem_u32(const void* p) {
    return (uint32_t)__cvta_generic_to_shared(p);
}
__device__ __forceinline__ void cp16(uint32_t saddr, const void* g) {
    asm volatile("cp.async.cg.shared.global [%0], [%1], 16;\n" :: "r"(saddr), "l"(g) : "memory");
}
#define CP_COMMIT() asm volatile("cp.async.commit_group;\n" ::: "memory")
#define CP_WAIT1()  asm volatile("cp.async.wait_group 1;\n" ::: "memory")

__device__ __forceinline__ float block_reduce_max(float v) {
    __shared__ float sh[32];
    int lane = threadIdx.x & 31, wid = threadIdx.x >> 5;
#pragma unroll
    for (int o = 16; o; o >>= 1) v = fmaxf(v, __shfl_xor_sync(0xffffffffu, v, o));
    if (lane == 0) sh[wid] = v;
    __syncthreads();
    int nw = blockDim.x >> 5;
    if (wid == 0) {
        v = (lane < nw) ? sh[lane] : 0.0f;
#pragma unroll
        for (int o = 16; o; o >>= 1) v = fmaxf(v, __shfl_xor_sync(0xffffffffu, v, o));
        if (lane == 0) sh[0] = v;
    }
    __syncthreads();
    return sh[0];
}

// quantize 4 floats to ternary bf16 pair-pack
__device__ __forceinline__ uint2 tern_pack(float4 v, float scale) {
    float q0 = fminf(fmaxf(rintf(v.x * scale), -1.f), 1.f);
    float q1 = fminf(fmaxf(rintf(v.y * scale), -1.f), 1.f);
    float q2 = fminf(fmaxf(rintf(v.z * scale), -1.f), 1.f);
    float q3 = fminf(fmaxf(rintf(v.w * scale), -1.f), 1.f);
    __nv_bfloat162 p0 = __floats2bfloat162_rn(q0, q1);
    __nv_bfloat162 p1 = __floats2bfloat162_rn(q2, q3);
    uint2 pk;
    pk.x = *reinterpret_cast<uint32_t*>(&p0);
    pk.y = *reinterpret_cast<uint32_t*>(&p1);
    return pk;
}

// ---------------- small kernels ----------------
__global__ void abssum_kernel(const float* __restrict__ w, int which) {
    const size_t n4 = W_ELEMS / 4;
    const float4* w4 = (const float4*)w;
    float s = 0.f;
    for (size_t i = blockIdx.x * (size_t)blockDim.x + threadIdx.x; i < n4;
         i += (size_t)gridDim.x * blockDim.x) {
        float4 v = w4[i];
        s += fabsf(v.x) + fabsf(v.y) + fabsf(v.z) + fabsf(v.w);
    }
    double d = (double)s;
#pragma unroll
    for (int o = 16; o; o >>= 1) d += __shfl_xor_sync(0xffffffffu, d, o);
    __shared__ double sh[32];
    int lane = threadIdx.x & 31, wid = threadIdx.x >> 5;
    if (lane == 0) sh[wid] = d;
    __syncthreads();
    if (wid == 0) {
        d = (lane < (int)(blockDim.x >> 5)) ? sh[lane] : 0.0;
#pragma unroll
        for (int o = 16; o; o >>= 1) d += __shfl_xor_sync(0xffffffffu, d, o);
        if (lane == 0) atomicAdd(&g_wsum[which], d);
    }
}

// computes dq[which], then resets wsum[which] for the next graph replay
__global__ void finalize_kernel(int which) {
    g_dq[which] = fmaxf((float)(g_wsum[which] / (double)W_ELEMS), EPSV);
    g_wsum[which] = 0.0;
}

__global__ void wquant_kernel(const float* __restrict__ w, int which) {
    __nv_bfloat16* q = which ? g_wq_dec : g_wq_enc;
    float scale = 1.0f / g_dq[which];
    const size_t n4 = W_ELEMS / 4;
    const float4* w4 = (const float4*)w;
    uint2* q4 = (uint2*)q;
    for (size_t i = blockIdx.x * (size_t)blockDim.x + threadIdx.x; i < n4;
         i += (size_t)gridDim.x * blockDim.x) {
        q4[i] = tern_pack(w4[i], scale);
    }
}

// independent of the weight chains (fmax reset lives here; wsum reset in finalize)
__global__ void xquant_kernel(const float* __restrict__ x, const float* __restrict__ dec_b) {
    int row = blockIdx.x;
    if (threadIdx.x == 0) g_fmax[row] = 0u;
    const float4* xr = (const float4*)(x + (size_t)row * F_DIM);
    const float4* db = (const float4*)dec_b;
    const int n4 = F_DIM / 4;
    float m = 0.f;
    for (int i = threadIdx.x; i < n4; i += blockDim.x) {
        float4 v = xr[i], b = db[i];
        m = fmaxf(m, fmaxf(fmaxf(fabsf(v.x - b.x), fabsf(v.y - b.y)),
                           fmaxf(fabsf(v.z - b.z), fabsf(v.w - b.w))));
    }
    m = block_reduce_max(m);
    float scale = 127.0f / fmaxf(m, EPSV);
    if (threadIdx.x == 0) g_xinv[row] = 1.0f / scale;
    uint2* qr = (uint2*)(g_xq + (size_t)row * F_DIM);
    for (int i = threadIdx.x; i < n4; i += blockDim.x) {
        float4 v = xr[i], b = db[i];
        float q0 = fminf(fmaxf(rintf((v.x - b.x) * scale), -128.f), 127.f);
        float q1 = fminf(fmaxf(rintf((v.y - b.y) * scale), -128.f), 127.f);
        float q2 = fminf(fmaxf(rintf((v.z - b.z) * scale), -128.f), 127.f);
        float q3 = fminf(fmaxf(rintf((v.w - b.w) * scale), -128.f), 127.f);
        __nv_bfloat162 p0 = __floats2bfloat162_rn(q0, q1);
        __nv_bfloat162 p1 = __floats2bfloat162_rn(q2, q3);
        uint2 pk;
        pk.x = *reinterpret_cast<uint32_t*>(&p0);
        pk.y = *reinterpret_cast<uint32_t*>(&p1);
        qr[i] = pk;
    }
}

// single pass: row max from g_fmax (filled by enc epilogue)
__global__ void fquant_kernel(const float* __restrict__ f) {
    int row = blockIdx.x;
    const float4* fr = (const float4*)(f + (size_t)row * H_DIM);
    const int n4 = H_DIM / 4;
    float m = __uint_as_float(g_fmax[row]);
    float scale = 127.0f / fmaxf(m, EPSV);
    if (threadIdx.x == 0) g_finv[row] = 1.0f / scale;
    uint2* qr = (uint2*)(g_fq + (size_t)row * H_DIM);
    for (int i = threadIdx.x; i < n4; i += blockDim.x) {
        float4 v = fr[i];
        float q0 = fminf(fmaxf(rintf(v.x * scale), -128.f), 127.f);
        float q1 = fminf(fmaxf(rintf(v.y * scale), -128.f), 127.f);
        float q2 = fminf(fmaxf(rintf(v.z * scale), -128.f), 127.f);
        float q3 = fminf(fmaxf(rintf(v.w * scale), -128.f), 127.f);
        __nv_bfloat162 p0 = __floats2bfloat162_rn(q0, q1);
        __nv_bfloat162 p1 = __floats2bfloat162_rn(q2, q3);
        uint2 pk;
        pk.x = *reinterpret_cast<uint32_t*>(&p0);
        pk.y = *reinterpret_cast<uint32_t*>(&p1);
        qr[i] = pk;
    }
}

// ---------------- bf16 GEMM: CTA 128x128, 4 warps of 64x64, BK=64, 3-stage ----------
// MODE 0: enc epilogue (scale+bias+relu + row-max atomic). MODE 1: raw split-K partials.
#define BM 128
#define BN 128
#define BKB 128                            // bytes per row per stage (64 bf16)
#define NSTAGE 3
#define A_TILE_B (BM * BKB)                // 16 KB
#define STAGE_B (2 * A_TILE_B)             // 32 KB (A + B)
#define SMEM_GEMM (NSTAGE * STAGE_B)       // 96 KB

__device__ __forceinline__ uint32_t swz(uint32_t row, uint32_t colByte) {
    return row * 128u + (colByte ^ ((row & 7u) * 16u));
}

template <int MODE>
__global__ __launch_bounds__(128, 2)
void gemm_kernel(float* __restrict__ C, const float* __restrict__ bias,
                 int N, int K, int which) {
    extern __shared__ char smem[];
    const uint32_t sbase = smem_u32(smem);

    const __nv_bfloat16* __restrict__ A  = which ? g_fq     : g_xq;
    const __nv_bfloat16* __restrict__ Bw = which ? g_wq_dec : g_wq_enc;
    const float* __restrict__ rowScale   = which ? g_finv   : g_xinv;

    const int tid  = threadIdx.x;
    const int lane = tid & 31;
    const int warp = tid >> 5;     // 0..3
    const int wm = warp >> 1;      // 0..1
    const int wn = warp & 1;       // 0..1
    const int mBase = blockIdx.x * BM;
    const int nBase = blockIdx.y * BN;

    // split-K (MODE 1): z selects K half and partial buffer
    const int kOff = (MODE == 1) ? (int)blockIdx.z * (K >> 1) : 0;
    const int kLen = (MODE == 1) ? (K >> 1) : K;
    float* __restrict__ Cout = (MODE == 1)
        ? g_psum + (size_t)blockIdx.z * B_DIM * F_DIM : C;

    // ---- global->shared mapping: 128 threads, 8 chunks A + 8 chunks B per stage ----
    const int crow = tid >> 3;             // 0..15 (+16*i)
    const int ckb  = (tid & 7) * 16;       // byte within 128B row
    const size_t rowB = (size_t)K * 2;     // row stride bytes
    const char* gA = (const char*)A  + (size_t)(mBase + crow) * rowB + (size_t)kOff * 2 + ckb;
    const char* gB = (const char*)Bw + (size_t)(nBase + crow) * rowB + (size_t)kOff * 2 + ckb;
    const uint32_t sOff = swz(crow, ckb);  // row&7 invariant under +16*i

    uint32_t stage[NSTAGE];
#pragma unroll
    for (int s = 0; s < NSTAGE; s++) stage[s] = sbase + s * STAGE_B;

    const int nkt = kLen / 64;

    auto load_stage = [&](int slot, int kt) {
        const uint32_t sa = stage[slot] + sOff;
        const uint32_t sb = sa + A_TILE_B;
        const char* ga = gA + (size_t)kt * BKB;
        const char* gb = gB + (size_t)kt * BKB;
#pragma unroll
        for (int i = 0; i < 8; i++) {
            cp16(sa + i * (16 * 128), ga + (size_t)i * 16 * rowB);
            cp16(sb + i * (16 * 128), gb + (size_t)i * 16 * rowB);
        }
    };

    // ---- ldmatrix lane addressing ----
    const uint32_t aRow = wm * 64 + (lane & 15);                          // + mi*16
    const uint32_t aColH = (lane >> 4) * 16;                              // + ks*32
    const uint32_t bRow = wn * 64 + (lane & 7) + ((lane >> 4) & 1) * 8;   // + nb*16
    const uint32_t bColH = ((lane >> 3) & 1) * 16;                        // + ks*32

    float acc[4][8][4];
#pragma unroll
    for (int mi = 0; mi < 4; mi++)
#pragma unroll
        for (int ni = 0; ni < 8; ni++)
#pragma unroll
            for (int r = 0; r < 4; r++) acc[mi][ni][r] = 0.f;

    // ---- prologue: 2 stages in flight ----
    load_stage(0, 0); CP_COMMIT();
    if (nkt > 1) { load_stage(1, 1); }
    CP_COMMIT();

    int slot = 0;
    for (int kt = 0; kt < nkt; kt++) {
        CP_WAIT1();
        __syncthreads();

        // prefetch kt+2
        {
            const int ldk = kt + 2;
            if (ldk < nkt) {
                int ps = slot + 2; if (ps >= NSTAGE) ps -= NSTAGE;
                load_stage(ps, ldk);
            }
            CP_COMMIT();
        }

        const uint32_t sA = stage[slot];
        const uint32_t sB = stage[slot] + A_TILE_B;

#pragma unroll
        for (int ks = 0; ks < 4; ks++) {
            uint32_t a[4][4];
#pragma unroll
            for (int mi = 0; mi < 4; mi++) {
                const uint32_t addr = sA + swz(aRow + mi * 16, ks * 32 + aColH);
                asm volatile("ldmatrix.sync.aligned.m8n8.x4.shared.b16 {%0,%1,%2,%3}, [%4];\n"
                             : "=r"(a[mi][0]), "=r"(a[mi][1]), "=r"(a[mi][2]), "=r"(a[mi][3])
                             : "r"(addr));
            }
            uint32_t b[4][4];
#pragma unroll
            for (int nb = 0; nb < 4; nb++) {
                const uint32_t addr = sB + swz(bRow + nb * 16, ks * 32 + bColH);
                asm volatile("ldmatrix.sync.aligned.m8n8.x4.shared.b16 {%0,%1,%2,%3}, [%4];\n"
                             : "=r"(b[nb][0]), "=r"(b[nb][1]), "=r"(b[nb][2]), "=r"(b[nb][3])
                             : "r"(addr));
            }
#pragma unroll
            for (int mi = 0; mi < 4; mi++) {
#pragma unroll
                for (int ni = 0; ni < 8; ni++) {
                    const int nb = ni >> 1, pp = (ni & 1) * 2;
                    asm volatile(
                        "mma.sync.aligned.m16n8k16.row.col.f32.bf16.bf16.f32 "
                        "{%0,%1,%2,%3}, {%4,%5,%6,%7}, {%8,%9}, {%0,%1,%2,%3};\n"
                        : "+f"(acc[mi][ni][0]), "+f"(acc[mi][ni][1]),
                          "+f"(acc[mi][ni][2]), "+f"(acc[mi][ni][3])
                        : "r"(a[mi][0]), "r"(a[mi][1]), "r"(a[mi][2]), "r"(a[mi][3]),
                          "r"(b[nb][pp]), "r"(b[nb][pp + 1]));
                }
            }
        }
        if (++slot == NSTAGE) slot = 0;
    }

    // ---- epilogue ----
    const int r0 = mBase + wm * 64 + (lane >> 2);
    const int c0 = nBase + wn * 64 + (lane & 3) * 2;

    if (MODE == 1) {
        // raw split-K partials (exact integers in f32)
#pragma unroll
        for (int mi = 0; mi < 4; mi++) {
#pragma unroll
            for (int half = 0; half < 2; half++) {
                const int row = r0 + mi * 16 + half * 8;
                float* cp = Cout + (size_t)row * N;
#pragma unroll
                for (int ni = 0; ni < 8; ni++) {
                    const int col = c0 + ni * 8;
                    *reinterpret_cast<float2*>(cp + col) =
                        make_float2(acc[mi][ni][half * 2 + 0], acc[mi][ni][half * 2 + 1]);
                }
            }
        }
    } else {
        const float dq = g_dq[which];
#pragma unroll
        for (int mi = 0; mi < 4; mi++) {
#pragma unroll
            for (int half = 0; half < 2; half++) {
                const int row = r0 + mi * 16 + half * 8;
                const float s = rowScale[row] * dq;
                float* cp = Cout + (size_t)row * N;
                float rm = 0.f;
#pragma unroll
                for (int ni = 0; ni < 8; ni++) {
                    const int col = c0 + ni * 8;
                    float v0 = acc[mi][ni][half * 2 + 0] * s + bias[col];
                    float v1 = acc[mi][ni][half * 2 + 1] * s + bias[col + 1];
                    v0 = fmaxf(v0, 0.f); v1 = fmaxf(v1, 0.f);
                    rm = fmaxf(rm, fmaxf(v0, v1));
                    *reinterpret_cast<float2*>(cp + col) = make_float2(v0, v1);
                }
                // row max over the 4 lanes sharing this row, one atomic per row/warp
                rm = fmaxf(rm, __shfl_xor_sync(0xffffffffu, rm, 1));
                rm = fmaxf(rm, __shfl_xor_sync(0xffffffffu, rm, 2));
                if ((lane & 3) == 0) atomicMax(&g_fmax[row], __float_as_uint(rm));
            }
        }
    }
}

// dec finish: xhat = (p0 + p1) * rowScale + dec_b
__global__ void dec_finish(float* __restrict__ xhat, const float* __restrict__ dec_b) {
    const size_t i4 = blockIdx.x * (size_t)blockDim.x + threadIdx.x;   // float4 index
    const int row = (int)(i4 / (F_DIM / 4));
    const int c4 = (int)(i4 % (F_DIM / 4));
    const float s = g_finv[row] * g_dq[1];
    const float4 p0 = ((const float4*)g_psum)[i4];
    const float4 p1 = ((const float4*)g_psum)[i4 + (size_t)B_DIM * F_DIM / 4];
    const float4 b = ((const float4*)dec_b)[c4];
    float4 o;
    o.x = (p0.x + p1.x) * s + b.x;
    o.y = (p0.y + p1.y) * s + b.y;
    o.z = (p0.z + p1.z) * s + b.z;
    o.w = (p0.w + p1.w) * s + b.w;
    ((float4*)xhat)[i4] = o;
}

// ---------------- launch ----------------
extern "C" void kernel_launch(void* const* d_in, const int* in_sizes, int n_in,
                              void* d_out, int out_size) {
    (void)in_sizes; (void)n_in; (void)out_size;
    const float* x     = (const float*)d_in[0];
    const float* enc_w = (const float*)d_in[1];
    const float* enc_b = (const float*)d_in[2];
    const float* dec_w = (const float*)d_in[3];
    const float* dec_b = (const float*)d_in[4];

    float* xhat = (float*)d_out;                               // [B, F]
    float* fout = (float*)d_out + (size_t)B_DIM * F_DIM;       // [B, H]

    static int inited = 0;
    static cudaStream_t s2, s3;
    static cudaEvent_t eRoot, e0, e1, e2;
    if (!inited) {
        cudaFuncSetAttribute(gemm_kernel<0>, cudaFuncAttributeMaxDynamicSharedMemorySize, SMEM_GEMM);
        cudaFuncSetAttribute(gemm_kernel<1>, cudaFuncAttributeMaxDynamicSharedMemorySize, SMEM_GEMM);
        cudaStreamCreateWithFlags(&s2, cudaStreamNonBlocking);
        cudaStreamCreateWithFlags(&s3, cudaStreamNonBlocking);
        cudaEventCreateWithFlags(&eRoot, cudaEventDisableTiming);
        cudaEventCreateWithFlags(&e0, cudaEventDisableTiming);
        cudaEventCreateWithFlags(&e1, cudaEventDisableTiming);
        cudaEventCreateWithFlags(&e2, cudaEventDisableTiming);
        inited = 1;
    }

    // ---- root fork (capture-legal: s3 joins via event from the origin stream) ----
    cudaEventRecord(eRoot, 0);
    cudaStreamWaitEvent(s3, eRoot, 0);
    xquant_kernel<<<B_DIM, 512, 0, s3>>>(x, dec_b);
    cudaEventRecord(e0, s3);

    // ---- stream 0: enc-weight chain (parallel with xquant) ----
    abssum_kernel<<<2048, 256>>>(enc_w, 0);
    finalize_kernel<<<1, 1>>>(0);                                // dq[0], resets wsum[0]
    wquant_kernel<<<8192, 256>>>(enc_w, 0);

    // ---- fork: dec-weight branch runs concurrently with the enc GEMM ----
    cudaEventRecord(e1, 0);
    cudaStreamWaitEvent(s2, e1, 0);
    abssum_kernel<<<2048, 256, 0, s2>>>(dec_w, 1);
    finalize_kernel<<<1, 1, 0, s2>>>(1);                         // dq[1], resets wsum[1]
    wquant_kernel<<<8192, 256, 0, s2>>>(dec_w, 1);
    cudaEventRecord(e2, s2);

    // ---- stream 0: enc GEMM (needs xquant done) ----
    cudaStreamWaitEvent(0, e0, 0);
    {
        dim3 grid(B_DIM / BM, H_DIM / BN);
        gemm_kernel<0><<<grid, 128, SMEM_GEMM>>>(fout, enc_b, H_DIM, F_DIM, 0);
    }
    fquant_kernel<<<B_DIM, 512>>>(fout);

    // ---- join, then dec GEMM (split-K=2) + finish ----
    cudaStreamWaitEvent(0, e2, 0);
    {
        dim3 grid(B_DIM / BM, F_DIM / BN, 2);
        gemm_kernel<1><<<grid, 128, SMEM_GEMM>>>(nullptr, nullptr, F_DIM, H_DIM, 1);
        dec_finish<<<(B_DIM * (F_DIM / 4)) / 256, 256>>>(xhat, dec_b);
    }
}

// round 17
// speedup vs baseline: 1.1396x; 1.0042x over previous
#include <cuda_runtime.h>
#include <cuda_bf16.h>
#include <cstdint>

#define EPSV 1e-5f
#define B_DIM 4096
#define F_DIM 4096
#define H_DIM 32768
#define W_ELEMS ((size_t)H_DIM * (size_t)F_DIM)   // 134217728

// ---------------- scratch (device globals: no allocation allowed) ----------------
__device__ __nv_bfloat16 g_wq_enc[W_ELEMS];                    // ternary enc_w bf16 [H,F]
__device__ __nv_bfloat16 g_wq_dec[W_ELEMS];                    // ternary dec_w bf16 [F,H]
__device__ __nv_bfloat16 g_xq[(size_t)B_DIM * F_DIM];          // int-valued x bf16 [B,F]
__device__ __nv_bfloat16 g_fq[(size_t)B_DIM * H_DIM];          // int-valued f bf16 [B,H]
__device__ float  g_psum[2ull * B_DIM * F_DIM];                // dec split-K partials
__device__ float  g_xinv[B_DIM];
__device__ float  g_finv[B_DIM];
__device__ unsigned g_fmax[B_DIM];                             // row max of f (uint bits)
__device__ double g_wsum[2];                                   // 0 at load; finalize resets after use
__device__ float  g_dq[2];

// ---------------- helpers ----------------
__device__ __forceinline__ uint32_t smem_u32(const void* p) {
    return (uint32_t)__cvta_generic_to_shared(p);
}
__device__ __forceinline__ void cp16(uint32_t saddr, const void* g) {
    asm volatile("cp.async.cg.shared.global [%0], [%1], 16;\n" :: "r"(saddr), "l"(g) : "memory");
}
#define CP_COMMIT() asm volatile("cp.async.commit_group;\n" ::: "memory")
#define CP_WAIT1()  asm volatile("cp.async.wait_group 1;\n" ::: "memory")

__device__ __forceinline__ float block_reduce_max(float v) {
    __shared__ float sh[32];
    int lane = threadIdx.x & 31, wid = threadIdx.x >> 5;
#pragma unroll
    for (int o = 16; o; o >>= 1) v = fmaxf(v, __shfl_xor_sync(0xffffffffu, v, o));
    if (lane == 0) sh[wid] = v;
    __syncthreads();
    int nw = blockDim.x >> 5;
    if (wid == 0) {
        v = (lane < nw) ? sh[lane] : 0.0f;
#pragma unroll
        for (int o = 16; o; o >>= 1) v = fmaxf(v, __shfl_xor_sync(0xffffffffu, v, o));
        if (lane == 0) sh[0] = v;
    }
    __syncthreads();
    return sh[0];
}

// quantize 4 floats to ternary bf16 pair-pack
__device__ __forceinline__ uint2 tern_pack(float4 v, float scale) {
    float q0 = fminf(fmaxf(rintf(v.x * scale), -1.f), 1.f);
    float q1 = fminf(fmaxf(rintf(v.y * scale), -1.f), 1.f);
    float q2 = fminf(fmaxf(rintf(v.z * scale), -1.f), 1.f);
    float q3 = fminf(fmaxf(rintf(v.w * scale), -1.f), 1.f);
    __nv_bfloat162 p0 = __floats2bfloat162_rn(q0, q1);
    __nv_bfloat162 p1 = __floats2bfloat162_rn(q2, q3);
    uint2 pk;
    pk.x = *reinterpret_cast<uint32_t*>(&p0);
    pk.y = *reinterpret_cast<uint32_t*>(&p1);
    return pk;
}

// ---------------- small kernels ----------------
__global__ void abssum_kernel(const float* __restrict__ w, int which) {
    const size_t n4 = W_ELEMS / 4;
    const float4* w4 = (const float4*)w;
    float s = 0.f;
    for (size_t i = blockIdx.x * (size_t)blockDim.x + threadIdx.x; i < n4;
         i += (size_t)gridDim.x * blockDim.x) {
        float4 v = w4[i];
        s += fabsf(v.x) + fabsf(v.y) + fabsf(v.z) + fabsf(v.w);
    }
    double d = (double)s;
#pragma unroll
    for (int o = 16; o; o >>= 1) d += __shfl_xor_sync(0xffffffffu, d, o);
    __shared__ double sh[32];
    int lane = threadIdx.x & 31, wid = threadIdx.x >> 5;
    if (lane == 0) sh[wid] = d;
    __syncthreads();
    if (wid == 0) {
        d = (lane < (int)(blockDim.x >> 5)) ? sh[lane] : 0.0;
#pragma unroll
        for (int o = 16; o; o >>= 1) d += __shfl_xor_sync(0xffffffffu, d, o);
        if (lane == 0) atomicAdd(&g_wsum[which], d);
    }
}

// computes dq[which], then resets wsum[which] for the next graph replay
__global__ void finalize_kernel(int which) {
    g_dq[which] = fmaxf((float)(g_wsum[which] / (double)W_ELEMS), EPSV);
    g_wsum[which] = 0.0;
}

__global__ void wquant_kernel(const float* __restrict__ w, int which) {
    __nv_bfloat16* q = which ? g_wq_dec : g_wq_enc;
    float scale = 1.0f / g_dq[which];
    const size_t n4 = W_ELEMS / 4;
    const float4* w4 = (const float4*)w;
    uint2* q4 = (uint2*)q;
    for (size_t i = blockIdx.x * (size_t)blockDim.x + threadIdx.x; i < n4;
         i += (size_t)gridDim.x * blockDim.x) {
        q4[i] = tern_pack(w4[i], scale);
    }
}

// independent of the weight chains (fmax reset lives here; wsum reset in finalize)
__global__ void xquant_kernel(const float* __restrict__ x, const float* __restrict__ dec_b) {
    int row = blockIdx.x;
    if (threadIdx.x == 0) g_fmax[row] = 0u;
    const float4* xr = (const float4*)(x + (size_t)row * F_DIM);
    const float4* db = (const float4*)dec_b;
    const int n4 = F_DIM / 4;
    float m = 0.f;
    for (int i = threadIdx.x; i < n4; i += blockDim.x) {
        float4 v = xr[i], b = db[i];
        m = fmaxf(m, fmaxf(fmaxf(fabsf(v.x - b.x), fabsf(v.y - b.y)),
                           fmaxf(fabsf(v.z - b.z), fabsf(v.w - b.w))));
    }
    m = block_reduce_max(m);
    float scale = 127.0f / fmaxf(m, EPSV);
    if (threadIdx.x == 0) g_xinv[row] = 1.0f / scale;
    uint2* qr = (uint2*)(g_xq + (size_t)row * F_DIM);
    for (int i = threadIdx.x; i < n4; i += blockDim.x) {
        float4 v = xr[i], b = db[i];
        float q0 = fminf(fmaxf(rintf((v.x - b.x) * scale), -128.f), 127.f);
        float q1 = fminf(fmaxf(rintf((v.y - b.y) * scale), -128.f), 127.f);
        float q2 = fminf(fmaxf(rintf((v.z - b.z) * scale), -128.f), 127.f);
        float q3 = fminf(fmaxf(rintf((v.w - b.w) * scale), -128.f), 127.f);
        __nv_bfloat162 p0 = __floats2bfloat162_rn(q0, q1);
        __nv_bfloat162 p1 = __floats2bfloat162_rn(q2, q3);
        uint2 pk;
        pk.x = *reinterpret_cast<uint32_t*>(&p0);
        pk.y = *reinterpret_cast<uint32_t*>(&p1);
        qr[i] = pk;
    }
}

// rows [rowBase, rowBase + gridDim.x): row max from g_fmax (filled by enc epilogue)
__global__ void fquant_kernel(const float* __restrict__ f, int rowBase) {
    int row = rowBase + blockIdx.x;
    const float4* fr = (const float4*)(f + (size_t)row * H_DIM);
    const int n4 = H_DIM / 4;
    float m = __uint_as_float(g_fmax[row]);
    float scale = 127.0f / fmaxf(m, EPSV);
    if (threadIdx.x == 0) g_finv[row] = 1.0f / scale;
    uint2* qr = (uint2*)(g_fq + (size_t)row * H_DIM);
    for (int i = threadIdx.x; i < n4; i += blockDim.x) {
        float4 v = fr[i];
        float q0 = fminf(fmaxf(rintf(v.x * scale), -128.f), 127.f);
        float q1 = fminf(fmaxf(rintf(v.y * scale), -128.f), 127.f);
        float q2 = fminf(fmaxf(rintf(v.z * scale), -128.f), 127.f);
        float q3 = fminf(fmaxf(rintf(v.w * scale), -128.f), 127.f);
        __nv_bfloat162 p0 = __floats2bfloat162_rn(q0, q1);
        __nv_bfloat162 p1 = __floats2bfloat162_rn(q2, q3);
        uint2 pk;
        pk.x = *reinterpret_cast<uint32_t*>(&p0);
        pk.y = *reinterpret_cast<uint32_t*>(&p1);
        qr[i] = pk;
    }
}

// ---------------- bf16 GEMM: CTA 128x128, 4 warps of 64x64, BK=64, 3-stage ----------
// MODE 0: enc epilogue (scale+bias+relu + row-max atomic). MODE 1: raw split-K partials.
#define BM 128
#define BN 128
#define BKB 128                            // bytes per row per stage (64 bf16)
#define NSTAGE 3
#define A_TILE_B (BM * BKB)                // 16 KB
#define STAGE_B (2 * A_TILE_B)             // 32 KB (A + B)
#define SMEM_GEMM (NSTAGE * STAGE_B)       // 96 KB

__device__ __forceinline__ uint32_t swz(uint32_t row, uint32_t colByte) {
    return row * 128u + (colByte ^ ((row & 7u) * 16u));
}

template <int MODE>
__global__ __launch_bounds__(128, 2)
void gemm_kernel(float* __restrict__ C, const float* __restrict__ bias,
                 int N, int K, int which, int mOff) {
    extern __shared__ char smem[];
    const uint32_t sbase = smem_u32(smem);

    const __nv_bfloat16* __restrict__ A  = which ? g_fq     : g_xq;
    const __nv_bfloat16* __restrict__ Bw = which ? g_wq_dec : g_wq_enc;
    const float* __restrict__ rowScale   = which ? g_finv   : g_xinv;

    const int tid  = threadIdx.x;
    const int lane = tid & 31;
    const int warp = tid >> 5;     // 0..3
    const int wm = warp >> 1;      // 0..1
    const int wn = warp & 1;       // 0..1
    const int mBase = ((int)blockIdx.x + mOff) * BM;
    const int nBase = blockIdx.y * BN;

    // split-K (MODE 1): z selects K half and partial buffer
    const int kOff = (MODE == 1) ? (int)blockIdx.z * (K >> 1) : 0;
    const int kLen = (MODE == 1) ? (K >> 1) : K;
    float* __restrict__ Cout = (MODE == 1)
        ? g_psum + (size_t)blockIdx.z * B_DIM * F_DIM : C;

    // ---- global->shared mapping: 128 threads, 8 chunks A + 8 chunks B per stage ----
    const int crow = tid >> 3;             // 0..15 (+16*i)
    const int ckb  = (tid & 7) * 16;       // byte within 128B row
    const size_t rowB = (size_t)K * 2;     // row stride bytes
    const char* gA = (const char*)A  + (size_t)(mBase + crow) * rowB + (size_t)kOff * 2 + ckb;
    const char* gB = (const char*)Bw + (size_t)(nBase + crow) * rowB + (size_t)kOff * 2 + ckb;
    const uint32_t sOff = swz(crow, ckb);  // row&7 invariant under +16*i

    uint32_t stage[NSTAGE];
#pragma unroll
    for (int s = 0; s < NSTAGE; s++) stage[s] = sbase + s * STAGE_B;

    const int nkt = kLen / 64;

    auto load_stage = [&](int slot, int kt) {
        const uint32_t sa = stage[slot] + sOff;
        const uint32_t sb = sa + A_TILE_B;
        const char* ga = gA + (size_t)kt * BKB;
        const char* gb = gB + (size_t)kt * BKB;
#pragma unroll
        for (int i = 0; i < 8; i++) {
            cp16(sa + i * (16 * 128), ga + (size_t)i * 16 * rowB);
            cp16(sb + i * (16 * 128), gb + (size_t)i * 16 * rowB);
        }
    };

    // ---- ldmatrix lane addressing ----
    const uint32_t aRow = wm * 64 + (lane & 15);                          // + mi*16
    const uint32_t aColH = (lane >> 4) * 16;                              // + ks*32
    const uint32_t bRow = wn * 64 + (lane & 7) + ((lane >> 4) & 1) * 8;   // + nb*16
    const uint32_t bColH = ((lane >> 3) & 1) * 16;                        // + ks*32

    float acc[4][8][4];
#pragma unroll
    for (int mi = 0; mi < 4; mi++)
#pragma unroll
        for (int ni = 0; ni < 8; ni++)
#pragma unroll
            for (int r = 0; r < 4; r++) acc[mi][ni][r] = 0.f;

    // ---- prologue: 2 stages in flight ----
    load_stage(0, 0); CP_COMMIT();
    if (nkt > 1) { load_stage(1, 1); }
    CP_COMMIT();

    int slot = 0;
    for (int kt = 0; kt < nkt; kt++) {
        CP_WAIT1();
        __syncthreads();

        // prefetch kt+2
        {
            const int ldk = kt + 2;
            if (ldk < nkt) {
                int ps = slot + 2; if (ps >= NSTAGE) ps -= NSTAGE;
                load_stage(ps, ldk);
            }
            CP_COMMIT();
        }

        const uint32_t sA = stage[slot];
        const uint32_t sB = stage[slot] + A_TILE_B;

#pragma unroll
        for (int ks = 0; ks < 4; ks++) {
            uint32_t a[4][4];
#pragma unroll
            for (int mi = 0; mi < 4; mi++) {
                const uint32_t addr = sA + swz(aRow + mi * 16, ks * 32 + aColH);
                asm volatile("ldmatrix.sync.aligned.m8n8.x4.shared.b16 {%0,%1,%2,%3}, [%4];\n"
                             : "=r"(a[mi][0]), "=r"(a[mi][1]), "=r"(a[mi][2]), "=r"(a[mi][3])
                             : "r"(addr));
            }
            uint32_t b[4][4];
#pragma unroll
            for (int nb = 0; nb < 4; nb++) {
                const uint32_t addr = sB + swz(bRow + nb * 16, ks * 32 + bColH);
                asm volatile("ldmatrix.sync.aligned.m8n8.x4.shared.b16 {%0,%1,%2,%3}, [%4];\n"
                             : "=r"(b[nb][0]), "=r"(b[nb][1]), "=r"(b[nb][2]), "=r"(b[nb][3])
                             : "r"(addr));
            }
#pragma unroll
            for (int mi = 0; mi < 4; mi++) {
#pragma unroll
                for (int ni = 0; ni < 8; ni++) {
                    const int nb = ni >> 1, pp = (ni & 1) * 2;
                    asm volatile(
                        "mma.sync.aligned.m16n8k16.row.col.f32.bf16.bf16.f32 "
                        "{%0,%1,%2,%3}, {%4,%5,%6,%7}, {%8,%9}, {%0,%1,%2,%3};\n"
                        : "+f"(acc[mi][ni][0]), "+f"(acc[mi][ni][1]),
                          "+f"(acc[mi][ni][2]), "+f"(acc[mi][ni][3])
                        : "r"(a[mi][0]), "r"(a[mi][1]), "r"(a[mi][2]), "r"(a[mi][3]),
                          "r"(b[nb][pp]), "r"(b[nb][pp + 1]));
                }
            }
        }
        if (++slot == NSTAGE) slot = 0;
    }

    // ---- epilogue ----
    const int r0 = mBase + wm * 64 + (lane >> 2);
    const int c0 = nBase + wn * 64 + (lane & 3) * 2;

    if (MODE == 1) {
        // raw split-K partials (exact integers in f32)
#pragma unroll
        for (int mi = 0; mi < 4; mi++) {
#pragma unroll
            for (int half = 0; half < 2; half++) {
                const int row = r0 + mi * 16 + half * 8;
                float* cp = Cout + (size_t)row * N;
#pragma unroll
                for (int ni = 0; ni < 8; ni++) {
                    const int col = c0 + ni * 8;
                    *reinterpret_cast<float2*>(cp + col) =
                        make_float2(acc[mi][ni][half * 2 + 0], acc[mi][ni][half * 2 + 1]);
                }
            }
        }
    } else {
        const float dq = g_dq[which];
#pragma unroll
        for (int mi = 0; mi < 4; mi++) {
#pragma unroll
            for (int half = 0; half < 2; half++) {
                const int row = r0 + mi * 16 + half * 8;
                const float s = rowScale[row] * dq;
                float* cp = Cout + (size_t)row * N;
                float rm = 0.f;
#pragma unroll
                for (int ni = 0; ni < 8; ni++) {
                    const int col = c0 + ni * 8;
                    float v0 = acc[mi][ni][half * 2 + 0] * s + bias[col];
                    float v1 = acc[mi][ni][half * 2 + 1] * s + bias[col + 1];
                    v0 = fmaxf(v0, 0.f); v1 = fmaxf(v1, 0.f);
                    rm = fmaxf(rm, fmaxf(v0, v1));
                    *reinterpret_cast<float2*>(cp + col) = make_float2(v0, v1);
                }
                // row max over the 4 lanes sharing this row, one atomic per row/warp
                rm = fmaxf(rm, __shfl_xor_sync(0xffffffffu, rm, 1));
                rm = fmaxf(rm, __shfl_xor_sync(0xffffffffu, rm, 2));
                if ((lane & 3) == 0) atomicMax(&g_fmax[row], __float_as_uint(rm));
            }
        }
    }
}

// dec finish over rows [rowBase, rowBase+2048): xhat = (p0 + p1) * rowScale + dec_b
__global__ void dec_finish(float* __restrict__ xhat, const float* __restrict__ dec_b,
                           int rowBase) {
    const size_t li4 = blockIdx.x * (size_t)blockDim.x + threadIdx.x;   // local float4 index
    const int row = rowBase + (int)(li4 / (F_DIM / 4));
    const int c4 = (int)(li4 % (F_DIM / 4));
    const size_t i4 = (size_t)row * (F_DIM / 4) + c4;
    const float s = g_finv[row] * g_dq[1];
    const float4 p0 = ((const float4*)g_psum)[i4];
    const float4 p1 = ((const float4*)g_psum)[i4 + (size_t)B_DIM * F_DIM / 4];
    const float4 b = ((const float4*)dec_b)[c4];
    float4 o;
    o.x = (p0.x + p1.x) * s + b.x;
    o.y = (p0.y + p1.y) * s + b.y;
    o.z = (p0.z + p1.z) * s + b.z;
    o.w = (p0.w + p1.w) * s + b.w;
    ((float4*)xhat)[i4] = o;
}

// ---------------- launch ----------------
extern "C" void kernel_launch(void* const* d_in, const int* in_sizes, int n_in,
                              void* d_out, int out_size) {
    (void)in_sizes; (void)n_in; (void)out_size;
    const float* x     = (const float*)d_in[0];
    const float* enc_w = (const float*)d_in[1];
    const float* enc_b = (const float*)d_in[2];
    const float* dec_w = (const float*)d_in[3];
    const float* dec_b = (const float*)d_in[4];

    float* xhat = (float*)d_out;                               // [B, F]
    float* fout = (float*)d_out + (size_t)B_DIM * F_DIM;       // [B, H]

    static int inited = 0;
    static cudaStream_t s2, s3;
    static cudaEvent_t eRoot, e0, e1, e2, eF0, e3;
    if (!inited) {
        cudaFuncSetAttribute(gemm_kernel<0>, cudaFuncAttributeMaxDynamicSharedMemorySize, SMEM_GEMM);
        cudaFuncSetAttribute(gemm_kernel<1>, cudaFuncAttributeMaxDynamicSharedMemorySize, SMEM_GEMM);
        cudaStreamCreateWithFlags(&s2, cudaStreamNonBlocking);
        cudaStreamCreateWithFlags(&s3, cudaStreamNonBlocking);
        cudaEventCreateWithFlags(&eRoot, cudaEventDisableTiming);
        cudaEventCreateWithFlags(&e0, cudaEventDisableTiming);
        cudaEventCreateWithFlags(&e1, cudaEventDisableTiming);
        cudaEventCreateWithFlags(&e2, cudaEventDisableTiming);
        cudaEventCreateWithFlags(&eF0, cudaEventDisableTiming);
        cudaEventCreateWithFlags(&e3, cudaEventDisableTiming);
        inited = 1;
    }

    // ---- root fork (capture-legal: s3 joins via event from the origin stream) ----
    cudaEventRecord(eRoot, 0);
    cudaStreamWaitEvent(s3, eRoot, 0);
    xquant_kernel<<<B_DIM, 512, 0, s3>>>(x, dec_b);
    cudaEventRecord(e0, s3);

    // ---- stream 0: enc-weight chain (parallel with xquant) ----
    abssum_kernel<<<2048, 256>>>(enc_w, 0);
    finalize_kernel<<<1, 1>>>(0);                                // dq[0], resets wsum[0]
    wquant_kernel<<<8192, 256>>>(enc_w, 0);

    // ---- fork: dec-weight branch runs concurrently with the enc GEMM ----
    cudaEventRecord(e1, 0);
    cudaStreamWaitEvent(s2, e1, 0);
    abssum_kernel<<<2048, 256, 0, s2>>>(dec_w, 1);
    finalize_kernel<<<1, 1, 0, s2>>>(1);                         // dq[1], resets wsum[1]
    wquant_kernel<<<8192, 256, 0, s2>>>(dec_w, 1);
    cudaEventRecord(e2, s2);

    // ---- stream 0: enc GEMM (needs xquant done) ----
    cudaStreamWaitEvent(0, e0, 0);
    {
        dim3 grid(B_DIM / BM, H_DIM / BN);
        gemm_kernel<0><<<grid, 128, SMEM_GEMM>>>(fout, enc_b, H_DIM, F_DIM, 0, 0);
    }

    // ---- pipelined fquant / dec GEMM halves ----
    fquant_kernel<<<B_DIM / 2, 512>>>(fout, 0);                  // rows [0, 2048)
    cudaEventRecord(eF0, 0);

    // s2: dec half 0 (m-tiles 0..15) after fquant half0 + dec weights (stream order)
    cudaStreamWaitEvent(s2, eF0, 0);
    {
        dim3 grid(B_DIM / BM / 2, F_DIM / BN, 2);
        gemm_kernel<1><<<grid, 128, SMEM_GEMM, s2>>>(nullptr, nullptr, F_DIM, H_DIM, 1, 0);
    }
    dec_finish<<<(2048 * (F_DIM / 4)) / 256, 256, 0, s2>>>(xhat, dec_b, 0);
    cudaEventRecord(e3, s2);

    // s0: fquant half1, then dec half 1 (m-tiles 16..31) after dec weights
    fquant_kernel<<<B_DIM / 2, 512>>>(fout, B_DIM / 2);          // rows [2048, 4096)
    cudaStreamWaitEvent(0, e2, 0);
    {
        dim3 grid(B_DIM / BM / 2, F_DIM / BN, 2);
        gemm_kernel<1><<<grid, 128, SMEM_GEMM>>>(nullptr, nullptr, F_DIM, H_DIM, 1,
                                                 B_DIM / BM / 2);
    }
    dec_finish<<<(2048 * (F_DIM / 4)) / 256, 256>>>(xhat, dec_b, B_DIM / 2);

    // ---- join s2 back into the origin stream ----
    cudaStreamWaitEvent(0, e3, 0);
}